// round 2
// baseline (speedup 1.0000x reference)
#include <cuda_runtime.h>
#include <math.h>

// Problem constants
#define L_    8
#define H_    16
#define E_    1024
#define T_    1024
#define B_    2
#define V_    800
#define D_    64
#define MTOK  2048      // B*T
#define FF    4096      // 4*E

// ---------------------------------------------------------------------------
// Scratch (device globals: allocation-free per harness rules)
// ---------------------------------------------------------------------------
__device__ float g_x[MTOK * E_];      // residual stream
__device__ float g_h[MTOK * E_];      // LN output
__device__ float g_q[MTOK * E_];
__device__ float g_k[MTOK * E_];
__device__ float g_v[MTOK * E_];
__device__ float g_attn[MTOK * E_];
__device__ float g_s[(size_t)B_ * H_ * T_ * T_];   // 128 MB score matrix
__device__ float g_mlp[MTOK * FF];                 // 32 MB

__device__ __forceinline__ float neg_inf() { return __int_as_float(0xff800000); }

// ---------------------------------------------------------------------------
// Embedding: x[b,t,:] = tok_table[tok] + lat*posW[0] + lon*posW[1] + posb
// ---------------------------------------------------------------------------
__global__ void embed_kernel(const float* __restrict__ idx,
                             const float* __restrict__ tok_table,
                             const float* __restrict__ posW,
                             const float* __restrict__ posb,
                             float* __restrict__ x) {
    int row = blockIdx.x;                       // b*T + t
    float lat = idx[row * 3 + 0];
    float lon = idx[row * 3 + 1];
    float wl  = idx[row * 3 + 2];
    float f = rintf(wl * 100.0f - 300.0f);      // round-half-even == jnp.round
    f = fminf(fmaxf(f, 0.0f), (float)(V_ - 1));
    int tok = (int)f;
    const float* te = tok_table + (size_t)tok * E_;
    for (int e = threadIdx.x; e < E_; e += blockDim.x) {
        x[(size_t)row * E_ + e] = te[e] + lat * posW[e] + lon * posW[E_ + e] + posb[e];
    }
}

// ---------------------------------------------------------------------------
// LayerNorm over last dim (E=1024), one block per row, 256 threads
// ---------------------------------------------------------------------------
__global__ void ln_kernel(const float* __restrict__ in,
                          const float* __restrict__ g,
                          const float* __restrict__ b,
                          float* __restrict__ out) {
    int row = blockIdx.x;
    int tid = threadIdx.x;
    const float* px = in + (size_t)row * E_;
    float vals[4];
    float s = 0.f, sq = 0.f;
#pragma unroll
    for (int i = 0; i < 4; i++) {
        float v = px[tid + i * 256];
        vals[i] = v;
        s += v;
        sq += v * v;
    }
    __shared__ float r1[256], r2[256];
    r1[tid] = s; r2[tid] = sq;
    __syncthreads();
    for (int o = 128; o > 0; o >>= 1) {
        if (tid < o) { r1[tid] += r1[tid + o]; r2[tid] += r2[tid + o]; }
        __syncthreads();
    }
    float mean = r1[0] * (1.0f / E_);
    float var  = r2[0] * (1.0f / E_) - mean * mean;
    float rstd = rsqrtf(var + 1e-5f);
#pragma unroll
    for (int i = 0; i < 4; i++) {
        int e = tid + i * 256;
        out[(size_t)row * E_ + e] = (vals[i] - mean) * rstd * g[e] + b[e];
    }
}

// ---------------------------------------------------------------------------
// Generic tiled SGEMM: C[M,N] = act( A[M,K] @ W[K,N] + bias + Cin )
// BM=128 BN=64 BK=16, 256 threads, 8x4 microtile per thread.
// Requirements: M % 128 == 0, K % 16 == 0, N % 4 == 0 (N may be non-mult of 64)
// ---------------------------------------------------------------------------
template <int RELU>
__global__ void __launch_bounds__(256) gemm_kernel(
    const float* __restrict__ A, const float* __restrict__ W,
    const float* __restrict__ bias, const float* __restrict__ Cin,
    float* __restrict__ C, int M, int N, int K) {
    __shared__ float As[16][128];   // [k][m]
    __shared__ float Bs[16][64];    // [k][n]
    int tid = threadIdx.x;
    int tx = tid & 15;              // n dim (x4)
    int ty = tid >> 4;              // m dim (x8)
    int m0 = blockIdx.y * 128;
    int n0 = blockIdx.x * 64;

    float acc[8][4];
#pragma unroll
    for (int i = 0; i < 8; i++)
#pragma unroll
        for (int j = 0; j < 4; j++) acc[i][j] = 0.f;

    for (int k0 = 0; k0 < K; k0 += 16) {
        // A tile: 128 rows x 16 cols = 512 float4 -> 2 per thread
#pragma unroll
        for (int p = 0; p < 2; p++) {
            int idx = tid + p * 256;
            int m = idx >> 2;
            int k4 = (idx & 3) * 4;
            float4 a4 = *(const float4*)(A + (size_t)(m0 + m) * K + k0 + k4);
            As[k4 + 0][m] = a4.x;
            As[k4 + 1][m] = a4.y;
            As[k4 + 2][m] = a4.z;
            As[k4 + 3][m] = a4.w;
        }
        // B tile: 16 rows x 64 cols = 256 float4 -> 1 per thread
        {
            int kk = tid >> 4;
            int n4 = (tid & 15) * 4;
            int n = n0 + n4;
            float4 b4 = make_float4(0.f, 0.f, 0.f, 0.f);
            if (n < N) b4 = *(const float4*)(W + (size_t)(k0 + kk) * N + n);
            *(float4*)&Bs[kk][n4] = b4;
        }
        __syncthreads();
#pragma unroll
        for (int kk = 0; kk < 16; kk++) {
            float4 a0 = *(float4*)&As[kk][ty * 8];
            float4 a1 = *(float4*)&As[kk][ty * 8 + 4];
            float4 bv = *(float4*)&Bs[kk][tx * 4];
            float a[8] = {a0.x, a0.y, a0.z, a0.w, a1.x, a1.y, a1.z, a1.w};
            float bb[4] = {bv.x, bv.y, bv.z, bv.w};
#pragma unroll
            for (int i = 0; i < 8; i++)
#pragma unroll
                for (int j = 0; j < 4; j++) acc[i][j] = fmaf(a[i], bb[j], acc[i][j]);
        }
        __syncthreads();
    }

#pragma unroll
    for (int i = 0; i < 8; i++) {
        int row = m0 + ty * 8 + i;
#pragma unroll
        for (int j = 0; j < 4; j++) {
            int col = n0 + tx * 4 + j;
            if (col < N) {
                float v = acc[i][j];
                if (bias) v += bias[col];
                if (Cin) v += Cin[(size_t)row * N + col];
                if (RELU) v = fmaxf(v, 0.f);
                C[(size_t)row * N + col] = v;
            }
        }
    }
}

// ---------------------------------------------------------------------------
// Causal scores: S[bh,q,k] = (Q[b,q,h,:].K[b,k,h,:]) * 0.125, masked to -inf
// Block = 64x64 tile of S for one (b,h). Fully-masked tiles are fast-filled.
// ---------------------------------------------------------------------------
__global__ void __launch_bounds__(256) scores_kernel(
    const float* __restrict__ q, const float* __restrict__ k,
    float* __restrict__ s) {
    int bh = blockIdx.z;
    int b = bh >> 4;            // /H_
    int h = bh & 15;            // %H_
    int r0 = blockIdx.y * 64;
    int c0 = blockIdx.x * 64;
    float* Sp = s + (size_t)bh * T_ * T_;
    int tid = threadIdx.x;

    if (c0 > r0 + 63) {         // fully above diagonal: mask-fill
        float ni = neg_inf();
#pragma unroll
        for (int p = 0; p < 16; p++) {
            int idx = tid + p * 256;
            int rr = idx >> 6, cc = idx & 63;
            Sp[(size_t)(r0 + rr) * T_ + c0 + cc] = ni;
        }
        return;
    }

    __shared__ float Qs[64][65];
    __shared__ float Ks[64][65];
    const float* Qb = q + ((size_t)b * T_ + r0) * E_ + h * D_;
    const float* Kb = k + ((size_t)b * T_ + c0) * E_ + h * D_;
#pragma unroll
    for (int p = 0; p < 4; p++) {
        int idx = tid + p * 256;
        int rr = idx >> 4;
        int c4 = (idx & 15) * 4;
        float4 qa = *(const float4*)(Qb + (size_t)rr * E_ + c4);
        Qs[rr][c4] = qa.x; Qs[rr][c4 + 1] = qa.y; Qs[rr][c4 + 2] = qa.z; Qs[rr][c4 + 3] = qa.w;
        float4 ka = *(const float4*)(Kb + (size_t)rr * E_ + c4);
        Ks[rr][c4] = ka.x; Ks[rr][c4 + 1] = ka.y; Ks[rr][c4 + 2] = ka.z; Ks[rr][c4 + 3] = ka.w;
    }
    __syncthreads();

    int tx = tid & 15, ty = tid >> 4;
    float acc[4][4];
#pragma unroll
    for (int i = 0; i < 4; i++)
#pragma unroll
        for (int j = 0; j < 4; j++) acc[i][j] = 0.f;
#pragma unroll 8
    for (int kk = 0; kk < 64; kk++) {
        float a[4], bv[4];
#pragma unroll
        for (int i = 0; i < 4; i++) a[i] = Qs[ty * 4 + i][kk];
#pragma unroll
        for (int j = 0; j < 4; j++) bv[j] = Ks[tx * 4 + j][kk];
#pragma unroll
        for (int i = 0; i < 4; i++)
#pragma unroll
            for (int j = 0; j < 4; j++) acc[i][j] = fmaf(a[i], bv[j], acc[i][j]);
    }
    const float scale = 0.125f;   // D^-0.5
    float ni = neg_inf();
#pragma unroll
    for (int i = 0; i < 4; i++) {
        int rr = r0 + ty * 4 + i;
#pragma unroll
        for (int j = 0; j < 4; j++) {
            int cc = c0 + tx * 4 + j;
            Sp[(size_t)rr * T_ + cc] = (cc <= rr) ? acc[i][j] * scale : ni;
        }
    }
}

// ---------------------------------------------------------------------------
// Row softmax over T=1024, one block (256 threads) per row
// ---------------------------------------------------------------------------
__global__ void softmax_kernel(float* __restrict__ s) {
    size_t row = blockIdx.x;
    float* p = s + row * (size_t)T_;
    int tid = threadIdx.x;
    float v[4];
    float mx = neg_inf();
#pragma unroll
    for (int i = 0; i < 4; i++) {
        v[i] = p[tid + i * 256];
        mx = fmaxf(mx, v[i]);
    }
    __shared__ float red[256];
    red[tid] = mx;
    __syncthreads();
    for (int o = 128; o > 0; o >>= 1) {
        if (tid < o) red[tid] = fmaxf(red[tid], red[tid + o]);
        __syncthreads();
    }
    mx = red[0];
    __syncthreads();
    float sum = 0.f;
#pragma unroll
    for (int i = 0; i < 4; i++) {
        v[i] = expf(v[i] - mx);
        sum += v[i];
    }
    red[tid] = sum;
    __syncthreads();
    for (int o = 128; o > 0; o >>= 1) {
        if (tid < o) red[tid] += red[tid + o];
        __syncthreads();
    }
    float inv = 1.0f / red[0];
#pragma unroll
    for (int i = 0; i < 4; i++) p[tid + i * 256] = v[i] * inv;
}

// ---------------------------------------------------------------------------
// attn[b,q,h,:] = P[bh,q,:] @ V[b,:,h,:]   (causal: k < r0+64 only)
// Block = 64 q-rows x 64 head-dims for one (b,h)
// ---------------------------------------------------------------------------
__global__ void __launch_bounds__(256) pv_kernel(
    const float* __restrict__ s, const float* __restrict__ v,
    float* __restrict__ attn) {
    int bh = blockIdx.z;
    int b = bh >> 4, h = bh & 15;
    int r0 = blockIdx.y * 64;
    const float* Sp = s + (size_t)bh * T_ * T_;
    const float* Vb = v + (size_t)b * T_ * E_ + h * D_;
    __shared__ float As[16][65];  // [k][m]
    __shared__ float Bs[16][68];  // [k][n]
    int tid = threadIdx.x;
    int tx = tid & 15, ty = tid >> 4;
    float acc[4][4];
#pragma unroll
    for (int i = 0; i < 4; i++)
#pragma unroll
        for (int j = 0; j < 4; j++) acc[i][j] = 0.f;

    int kend = r0 + 64;           // causal truncation
    for (int k0 = 0; k0 < kend; k0 += 16) {
        {   // P tile: 64 rows x 16 cols = 256 float4
            int m = tid >> 2;
            int k4 = (tid & 3) * 4;
            float4 a4 = *(const float4*)(Sp + (size_t)(r0 + m) * T_ + k0 + k4);
            As[k4 + 0][m] = a4.x;
            As[k4 + 1][m] = a4.y;
            As[k4 + 2][m] = a4.z;
            As[k4 + 3][m] = a4.w;
        }
        {   // V tile: 16 rows (stride E) x 64 cols
            int kk = tid >> 4;
            int n4 = (tid & 15) * 4;
            float4 b4 = *(const float4*)(Vb + (size_t)(k0 + kk) * E_ + n4);
            *(float4*)&Bs[kk][n4] = b4;
        }
        __syncthreads();
#pragma unroll
        for (int kk = 0; kk < 16; kk++) {
            float a[4], bv[4];
#pragma unroll
            for (int i = 0; i < 4; i++) a[i] = As[kk][ty * 4 + i];
#pragma unroll
            for (int j = 0; j < 4; j++) bv[j] = Bs[kk][tx * 4 + j];
#pragma unroll
            for (int i = 0; i < 4; i++)
#pragma unroll
                for (int j = 0; j < 4; j++) acc[i][j] = fmaf(a[i], bv[j], acc[i][j]);
        }
        __syncthreads();
    }
    float* Ob = attn + (size_t)b * T_ * E_ + h * D_;
#pragma unroll
    for (int i = 0; i < 4; i++)
#pragma unroll
        for (int j = 0; j < 4; j++)
            Ob[(size_t)(r0 + ty * 4 + i) * E_ + tx * 4 + j] = acc[i][j];
}

// ---------------------------------------------------------------------------
// Launch
// ---------------------------------------------------------------------------
extern "C" void kernel_launch(void* const* d_in, const int* in_sizes, int n_in,
                              void* d_out, int out_size) {
    const float* idx  = (const float*)d_in[0];
    const float* tok  = (const float*)d_in[1];
    const float* posW = (const float*)d_in[2];
    const float* posb = (const float*)d_in[3];
    const float* Wq   = (const float*)d_in[4];
    const float* Wk   = (const float*)d_in[5];
    const float* Wv   = (const float*)d_in[6];
    const float* Wo   = (const float*)d_in[7];
    const float* bo   = (const float*)d_in[8];
    const float* W1   = (const float*)d_in[9];
    const float* b1   = (const float*)d_in[10];
    const float* W2   = (const float*)d_in[11];
    const float* b2   = (const float*)d_in[12];
    const float* ln1g = (const float*)d_in[13];
    const float* ln1b = (const float*)d_in[14];
    const float* ln2g = (const float*)d_in[15];
    const float* ln2b = (const float*)d_in[16];
    const float* lnfg = (const float*)d_in[17];
    const float* lnfb = (const float*)d_in[18];
    const float* lmW  = (const float*)d_in[19];
    const float* lmb  = (const float*)d_in[20];
    float* out = (float*)d_out;

    float *x, *h, *q, *k, *v, *attn, *s, *mlp;
    cudaGetSymbolAddress((void**)&x,    g_x);
    cudaGetSymbolAddress((void**)&h,    g_h);
    cudaGetSymbolAddress((void**)&q,    g_q);
    cudaGetSymbolAddress((void**)&k,    g_k);
    cudaGetSymbolAddress((void**)&v,    g_v);
    cudaGetSymbolAddress((void**)&attn, g_attn);
    cudaGetSymbolAddress((void**)&s,    g_s);
    cudaGetSymbolAddress((void**)&mlp,  g_mlp);

    embed_kernel<<<MTOK, 256>>>(idx, tok, posW, posb, x);

    dim3 gEE((E_ + 63) / 64, MTOK / 128);   // N=1024
    dim3 gEF((FF + 63) / 64, MTOK / 128);   // N=4096
    dim3 gV((V_ + 63) / 64, MTOK / 128);    // N=800
    dim3 gS(T_ / 64, T_ / 64, B_ * H_);
    dim3 gPV(1, T_ / 64, B_ * H_);

    for (int l = 0; l < L_; l++) {
        size_t oEE = (size_t)l * E_ * E_;
        size_t oEF = (size_t)l * E_ * FF;
        ln_kernel<<<MTOK, 256>>>(x, ln1g + l * E_, ln1b + l * E_, h);
        gemm_kernel<0><<<gEE, 256>>>(h, Wq + oEE, nullptr, nullptr, q, MTOK, E_, E_);
        gemm_kernel<0><<<gEE, 256>>>(h, Wk + oEE, nullptr, nullptr, k, MTOK, E_, E_);
        gemm_kernel<0><<<gEE, 256>>>(h, Wv + oEE, nullptr, nullptr, v, MTOK, E_, E_);
        scores_kernel<<<gS, 256>>>(q, k, s);
        softmax_kernel<<<B_ * H_ * T_, 256>>>(s);
        pv_kernel<<<gPV, 256>>>(s, v, attn);
        gemm_kernel<0><<<gEE, 256>>>(attn, Wo + oEE, bo + l * E_, x, x, MTOK, E_, E_);
        ln_kernel<<<MTOK, 256>>>(x, ln2g + l * E_, ln2b + l * E_, h);
        gemm_kernel<1><<<gEF, 256>>>(h, W1 + oEF, b1 + l * FF, nullptr, mlp, MTOK, FF, E_);
        gemm_kernel<0><<<gEE, 256>>>(mlp, W2 + oEF, b2 + l * E_, x, x, MTOK, E_, FF);
    }
    ln_kernel<<<MTOK, 256>>>(x, lnfg, lnfb, h);
    gemm_kernel<0><<<gV, 256>>>(h, lmW, lmb, nullptr, out, MTOK, V_, E_);
}

// round 6
// speedup vs baseline: 1.5644x; 1.5644x over previous
#include <cuda_runtime.h>
#include <cuda_bf16.h>
#include <math.h>
#include <stdint.h>

// Problem constants
#define L_    8
#define H_    16
#define E_    1024
#define T_    1024
#define B_    2
#define V_    800
#define D_    64
#define MTOK  2048      // B*T
#define FF    4096      // 4*E

typedef __nv_bfloat16 bf16;

// ---------------------------------------------------------------------------
// Scratch (device globals: allocation-free per harness rules)
// ---------------------------------------------------------------------------
__device__ float g_x[MTOK * E_];                   // residual stream (fp32)
__device__ float g_q[MTOK * E_];
__device__ float g_k[MTOK * E_];
__device__ float g_v[MTOK * E_];
__device__ float g_s[(size_t)B_ * H_ * T_ * T_];   // 128 MB score matrix

// split-bf16 activations
__device__ bf16 g_h_h[MTOK * E_];
__device__ bf16 g_h_l[MTOK * E_];
__device__ bf16 g_attn_h[MTOK * E_];
__device__ bf16 g_attn_l[MTOK * E_];
__device__ bf16 g_mlp_h[(size_t)MTOK * FF];
__device__ bf16 g_mlp_l[(size_t)MTOK * FF];

// split + transposed weights  ([N][K] row-major)
__device__ bf16 g_wq_h[(size_t)L_ * E_ * E_];
__device__ bf16 g_wq_l[(size_t)L_ * E_ * E_];
__device__ bf16 g_wk_h[(size_t)L_ * E_ * E_];
__device__ bf16 g_wk_l[(size_t)L_ * E_ * E_];
__device__ bf16 g_wv_h[(size_t)L_ * E_ * E_];
__device__ bf16 g_wv_l[(size_t)L_ * E_ * E_];
__device__ bf16 g_wo_h[(size_t)L_ * E_ * E_];
__device__ bf16 g_wo_l[(size_t)L_ * E_ * E_];
__device__ bf16 g_w1_h[(size_t)L_ * E_ * FF];
__device__ bf16 g_w1_l[(size_t)L_ * E_ * FF];
__device__ bf16 g_w2_h[(size_t)L_ * E_ * FF];
__device__ bf16 g_w2_l[(size_t)L_ * E_ * FF];
__device__ bf16 g_lm_h[(size_t)E_ * V_];
__device__ bf16 g_lm_l[(size_t)E_ * V_];

__device__ __forceinline__ float neg_inf() { return __int_as_float(0xff800000); }

__device__ __forceinline__ void split2(float v, bf16& h, bf16& l) {
    h = __float2bfloat16_rn(v);
    l = __float2bfloat16_rn(v - __bfloat162float(h));
}

// ---------------------------------------------------------------------------
// Transpose + split: W[K][N] fp32 -> Th/Tl [N][K] bf16.  K,N multiples of 32.
// ---------------------------------------------------------------------------
__global__ void tsplit_kernel(const float* __restrict__ W,
                              bf16* __restrict__ Th, bf16* __restrict__ Tl,
                              int K, int N) {
    __shared__ float t[32][33];
    int n0 = blockIdx.x * 32, k0 = blockIdx.y * 32;
    int tx = threadIdx.x, ty = threadIdx.y;   // 32 x 8
#pragma unroll
    for (int r = 0; r < 4; r++)
        t[ty + r * 8][tx] = W[(size_t)(k0 + ty + r * 8) * N + n0 + tx];
    __syncthreads();
#pragma unroll
    for (int r = 0; r < 4; r++) {
        int n = n0 + ty + r * 8;
        int k = k0 + tx;
        float v = t[tx][ty + r * 8];
        bf16 h, l; split2(v, h, l);
        Th[(size_t)n * K + k] = h;
        Tl[(size_t)n * K + k] = l;
    }
}

// ---------------------------------------------------------------------------
// Embedding (fp32 residual)
// ---------------------------------------------------------------------------
__global__ void embed_kernel(const float* __restrict__ idx,
                             const float* __restrict__ tok_table,
                             const float* __restrict__ posW,
                             const float* __restrict__ posb,
                             float* __restrict__ x) {
    int row = blockIdx.x;
    float lat = idx[row * 3 + 0];
    float lon = idx[row * 3 + 1];
    float wl  = idx[row * 3 + 2];
    float f = rintf(wl * 100.0f - 300.0f);
    f = fminf(fmaxf(f, 0.0f), (float)(V_ - 1));
    int tok = (int)f;
    const float* te = tok_table + (size_t)tok * E_;
    for (int e = threadIdx.x; e < E_; e += blockDim.x)
        x[(size_t)row * E_ + e] = te[e] + lat * posW[e] + lon * posW[E_ + e] + posb[e];
}

// ---------------------------------------------------------------------------
// LayerNorm -> split-bf16 output
// ---------------------------------------------------------------------------
__global__ void ln_split_kernel(const float* __restrict__ in,
                                const float* __restrict__ g,
                                const float* __restrict__ b,
                                bf16* __restrict__ oh, bf16* __restrict__ ol) {
    int row = blockIdx.x;
    int tid = threadIdx.x;
    const float* px = in + (size_t)row * E_;
    float vals[4];
    float s = 0.f, sq = 0.f;
#pragma unroll
    for (int i = 0; i < 4; i++) {
        float v = px[tid + i * 256];
        vals[i] = v; s += v; sq += v * v;
    }
    __shared__ float r1[256], r2[256];
    r1[tid] = s; r2[tid] = sq;
    __syncthreads();
    for (int o = 128; o > 0; o >>= 1) {
        if (tid < o) { r1[tid] += r1[tid + o]; r2[tid] += r2[tid + o]; }
        __syncthreads();
    }
    float mean = r1[0] * (1.0f / E_);
    float var  = r2[0] * (1.0f / E_) - mean * mean;
    float rstd = rsqrtf(var + 1e-5f);
#pragma unroll
    for (int i = 0; i < 4; i++) {
        int e = tid + i * 256;
        float v = (vals[i] - mean) * rstd * g[e] + b[e];
        bf16 h, l; split2(v, h, l);
        oh[(size_t)row * E_ + e] = h;
        ol[(size_t)row * E_ + e] = l;
    }
}

// ---------------------------------------------------------------------------
// Split-precision bf16 tensor-core GEMM
//   C[M,N] = act( (Ah+Al)[M,K] @ (Bh+Bl)^T[N,K]^T + bias + Cin )
//   via Ah@Bh + Ah@Bl + Al@Bh (mma.m16n8k16, fp32 accum)
// BM=128 BN=128 BK=16, 256 threads, warp grid 2x4, warp tile 64x32.
// M % 128 == 0, K % 16 == 0; NGUARD handles N not multiple of 128.
// ---------------------------------------------------------------------------
#define MMA_BF16(c, a, b0v, b1v)                                              \
    asm volatile(                                                             \
        "mma.sync.aligned.m16n8k16.row.col.f32.bf16.bf16.f32 "                \
        "{%0,%1,%2,%3}, {%4,%5,%6,%7}, {%8,%9}, {%0,%1,%2,%3};\n"             \
        : "+f"((c)[0]), "+f"((c)[1]), "+f"((c)[2]), "+f"((c)[3])              \
        : "r"((a)[0]), "r"((a)[1]), "r"((a)[2]), "r"((a)[3]),                 \
          "r"(b0v), "r"(b1v))

template <int RELU, int SPLIT_OUT, int NGUARD>
__global__ void __launch_bounds__(256) mma_gemm(
    const bf16* __restrict__ Ah, const bf16* __restrict__ Al,
    const bf16* __restrict__ Bh, const bf16* __restrict__ Bl,   // [N][K]
    const float* __restrict__ bias, const float* __restrict__ Cin,
    float* __restrict__ Cf, bf16* __restrict__ Ch, bf16* __restrict__ Cl,
    int M, int N, int K) {
    // [stage][arr: Ah,Al,Bh,Bl][row][k]  — 49152 bytes
    __shared__ bf16 sm[2][4][128][24];
    const int tid  = threadIdx.x;
    const int lane = tid & 31;
    const int warp = tid >> 5;
    const int wm = warp >> 2;            // 0..1
    const int wn = warp & 3;             // 0..3
    const int gid = lane >> 2, t4 = lane & 3;
    const int m0 = blockIdx.y * 128, n0 = blockIdx.x * 128;

    const int lrow = tid >> 1;           // 0..127
    const int lseg = (tid & 1) * 8;      // k offset 0 / 8

    const bf16* gAh = Ah + (size_t)(m0 + lrow) * K + lseg;
    const bf16* gAl = Al + (size_t)(m0 + lrow) * K + lseg;
    const int   bn  = n0 + lrow;
    const bool  bok = NGUARD ? (bn < N) : true;
    const bf16* gBh = Bh + (size_t)(NGUARD ? (bok ? bn : 0) : bn) * K + lseg;
    const bf16* gBl = Bl + (size_t)(NGUARD ? (bok ? bn : 0) : bn) * K + lseg;

    float acc[4][4][4];
#pragma unroll
    for (int i = 0; i < 4; i++)
#pragma unroll
        for (int j = 0; j < 4; j++)
#pragma unroll
            for (int e = 0; e < 4; e++) acc[i][j][e] = 0.f;

    const int nk = K >> 4;
    uint4 vah, val_, vbh, vbl;

    // prologue: stage 0
    vah = *(const uint4*)(gAh);
    val_ = *(const uint4*)(gAl);
    vbh = bok ? *(const uint4*)(gBh) : make_uint4(0, 0, 0, 0);
    vbl = bok ? *(const uint4*)(gBl) : make_uint4(0, 0, 0, 0);
    *(uint4*)&sm[0][0][lrow][lseg] = vah;
    *(uint4*)&sm[0][1][lrow][lseg] = val_;
    *(uint4*)&sm[0][2][lrow][lseg] = vbh;
    *(uint4*)&sm[0][3][lrow][lseg] = vbl;
    __syncthreads();

    for (int kt = 0; kt < nk; kt++) {
        const bool more = (kt + 1) < nk;
        if (more) {
            int ko = (kt + 1) << 4;
            vah = *(const uint4*)(gAh + ko);
            val_ = *(const uint4*)(gAl + ko);
            vbh = bok ? *(const uint4*)(gBh + ko) : make_uint4(0, 0, 0, 0);
            vbl = bok ? *(const uint4*)(gBl + ko) : make_uint4(0, 0, 0, 0);
        }
        const int s = kt & 1;
        // A fragments (hi & lo) for this warp's 4 m-tiles
        uint32_t afh[4][4], afl[4][4];
#pragma unroll
        for (int i = 0; i < 4; i++) {
            int r = wm * 64 + i * 16 + gid;
            afh[i][0] = *(const uint32_t*)&sm[s][0][r][2 * t4];
            afh[i][1] = *(const uint32_t*)&sm[s][0][r + 8][2 * t4];
            afh[i][2] = *(const uint32_t*)&sm[s][0][r][2 * t4 + 8];
            afh[i][3] = *(const uint32_t*)&sm[s][0][r + 8][2 * t4 + 8];
            afl[i][0] = *(const uint32_t*)&sm[s][1][r][2 * t4];
            afl[i][1] = *(const uint32_t*)&sm[s][1][r + 8][2 * t4];
            afl[i][2] = *(const uint32_t*)&sm[s][1][r][2 * t4 + 8];
            afl[i][3] = *(const uint32_t*)&sm[s][1][r + 8][2 * t4 + 8];
        }
#pragma unroll
        for (int j = 0; j < 4; j++) {
            int nr = wn * 32 + j * 8 + gid;
            uint32_t bh0 = *(const uint32_t*)&sm[s][2][nr][2 * t4];
            uint32_t bh1 = *(const uint32_t*)&sm[s][2][nr][2 * t4 + 8];
            uint32_t bl0 = *(const uint32_t*)&sm[s][3][nr][2 * t4];
            uint32_t bl1 = *(const uint32_t*)&sm[s][3][nr][2 * t4 + 8];
#pragma unroll
            for (int i = 0; i < 4; i++) {
                MMA_BF16(acc[i][j], afh[i], bh0, bh1);
                MMA_BF16(acc[i][j], afh[i], bl0, bl1);
                MMA_BF16(acc[i][j], afl[i], bh0, bh1);
            }
        }
        if (more) {
            const int ns = (kt + 1) & 1;
            *(uint4*)&sm[ns][0][lrow][lseg] = vah;
            *(uint4*)&sm[ns][1][lrow][lseg] = val_;
            *(uint4*)&sm[ns][2][lrow][lseg] = vbh;
            *(uint4*)&sm[ns][3][lrow][lseg] = vbl;
        }
        __syncthreads();
    }

    // epilogue
#pragma unroll
    for (int i = 0; i < 4; i++) {
        int r = m0 + wm * 64 + i * 16 + gid;
#pragma unroll
        for (int j = 0; j < 4; j++) {
            int c = n0 + wn * 32 + j * 8 + 2 * t4;
#pragma unroll
            for (int e = 0; e < 4; e++) {
                int row = r + ((e >> 1) ? 8 : 0);
                int col = c + (e & 1);
                if (!NGUARD || col < N) {
                    float v = acc[i][j][e];
                    if (bias) v += bias[col];
                    if (Cin) v += Cin[(size_t)row * N + col];
                    if (RELU) v = fmaxf(v, 0.f);
                    if (SPLIT_OUT) {
                        bf16 h, l; split2(v, h, l);
                        Ch[(size_t)row * N + col] = h;
                        Cl[(size_t)row * N + col] = l;
                    } else {
                        Cf[(size_t)row * N + col] = v;
                    }
                }
            }
        }
    }
}

// ---------------------------------------------------------------------------
// Causal scores (fp32)
// ---------------------------------------------------------------------------
__global__ void __launch_bounds__(256) scores_kernel(
    const float* __restrict__ q, const float* __restrict__ k,
    float* __restrict__ s) {
    int bh = blockIdx.z;
    int b = bh >> 4, h = bh & 15;
    int r0 = blockIdx.y * 64;
    int c0 = blockIdx.x * 64;
    float* Sp = s + (size_t)bh * T_ * T_;
    int tid = threadIdx.x;

    if (c0 > r0 + 63) {
        float ni = neg_inf();
#pragma unroll
        for (int p = 0; p < 16; p++) {
            int idx = tid + p * 256;
            int rr = idx >> 6, cc = idx & 63;
            Sp[(size_t)(r0 + rr) * T_ + c0 + cc] = ni;
        }
        return;
    }

    __shared__ float Qs[64][65];
    __shared__ float Ks[64][65];
    const float* Qb = q + ((size_t)b * T_ + r0) * E_ + h * D_;
    const float* Kb = k + ((size_t)b * T_ + c0) * E_ + h * D_;
#pragma unroll
    for (int p = 0; p < 4; p++) {
        int idx = tid + p * 256;
        int rr = idx >> 4;
        int c4 = (idx & 15) * 4;
        float4 qa = *(const float4*)(Qb + (size_t)rr * E_ + c4);
        Qs[rr][c4] = qa.x; Qs[rr][c4 + 1] = qa.y; Qs[rr][c4 + 2] = qa.z; Qs[rr][c4 + 3] = qa.w;
        float4 ka = *(const float4*)(Kb + (size_t)rr * E_ + c4);
        Ks[rr][c4] = ka.x; Ks[rr][c4 + 1] = ka.y; Ks[rr][c4 + 2] = ka.z; Ks[rr][c4 + 3] = ka.w;
    }
    __syncthreads();

    int tx = tid & 15, ty = tid >> 4;
    float acc[4][4];
#pragma unroll
    for (int i = 0; i < 4; i++)
#pragma unroll
        for (int j = 0; j < 4; j++) acc[i][j] = 0.f;
#pragma unroll 8
    for (int kk = 0; kk < 64; kk++) {
        float a[4], bv[4];
#pragma unroll
        for (int i = 0; i < 4; i++) a[i] = Qs[ty * 4 + i][kk];
#pragma unroll
        for (int j = 0; j < 4; j++) bv[j] = Ks[tx * 4 + j][kk];
#pragma unroll
        for (int i = 0; i < 4; i++)
#pragma unroll
            for (int j = 0; j < 4; j++) acc[i][j] = fmaf(a[i], bv[j], acc[i][j]);
    }
    const float scale = 0.125f;
    float ni = neg_inf();
#pragma unroll
    for (int i = 0; i < 4; i++) {
        int rr = r0 + ty * 4 + i;
#pragma unroll
        for (int j = 0; j < 4; j++) {
            int cc = c0 + tx * 4 + j;
            Sp[(size_t)rr * T_ + cc] = (cc <= rr) ? acc[i][j] * scale : ni;
        }
    }
}

// ---------------------------------------------------------------------------
// Row softmax
// ---------------------------------------------------------------------------
__global__ void softmax_kernel(float* __restrict__ s) {
    size_t row = blockIdx.x;
    float* p = s + row * (size_t)T_;
    int tid = threadIdx.x;
    float v[4];
    float mx = neg_inf();
#pragma unroll
    for (int i = 0; i < 4; i++) {
        v[i] = p[tid + i * 256];
        mx = fmaxf(mx, v[i]);
    }
    __shared__ float red[256];
    red[tid] = mx;
    __syncthreads();
    for (int o = 128; o > 0; o >>= 1) {
        if (tid < o) red[tid] = fmaxf(red[tid], red[tid + o]);
        __syncthreads();
    }
    mx = red[0];
    __syncthreads();
    float sum = 0.f;
#pragma unroll
    for (int i = 0; i < 4; i++) {
        v[i] = expf(v[i] - mx);
        sum += v[i];
    }
    red[tid] = sum;
    __syncthreads();
    for (int o = 128; o > 0; o >>= 1) {
        if (tid < o) red[tid] += red[tid + o];
        __syncthreads();
    }
    float inv = 1.0f / red[0];
#pragma unroll
    for (int i = 0; i < 4; i++) p[tid + i * 256] = v[i] * inv;
}

// ---------------------------------------------------------------------------
// P@V -> split-bf16 attn output
// ---------------------------------------------------------------------------
__global__ void __launch_bounds__(256) pv_kernel(
    const float* __restrict__ s, const float* __restrict__ v,
    bf16* __restrict__ attnh, bf16* __restrict__ attnl) {
    int bh = blockIdx.z;
    int b = bh >> 4, h = bh & 15;
    int r0 = blockIdx.y * 64;
    const float* Sp = s + (size_t)bh * T_ * T_;
    const float* Vb = v + (size_t)b * T_ * E_ + h * D_;
    __shared__ float As[16][65];
    __shared__ float Bs[16][68];
    int tid = threadIdx.x;
    int tx = tid & 15, ty = tid >> 4;
    float acc[4][4];
#pragma unroll
    for (int i = 0; i < 4; i++)
#pragma unroll
        for (int j = 0; j < 4; j++) acc[i][j] = 0.f;

    int kend = r0 + 64;
    for (int k0 = 0; k0 < kend; k0 += 16) {
        {
            int m = tid >> 2;
            int k4 = (tid & 3) * 4;
            float4 a4 = *(const float4*)(Sp + (size_t)(r0 + m) * T_ + k0 + k4);
            As[k4 + 0][m] = a4.x; As[k4 + 1][m] = a4.y;
            As[k4 + 2][m] = a4.z; As[k4 + 3][m] = a4.w;
        }
        {
            int kk = tid >> 4;
            int n4 = (tid & 15) * 4;
            float4 b4 = *(const float4*)(Vb + (size_t)(k0 + kk) * E_ + n4);
            *(float4*)&Bs[kk][n4] = b4;
        }
        __syncthreads();
#pragma unroll
        for (int kk = 0; kk < 16; kk++) {
            float a[4], bv[4];
#pragma unroll
            for (int i = 0; i < 4; i++) a[i] = As[kk][ty * 4 + i];
#pragma unroll
            for (int j = 0; j < 4; j++) bv[j] = Bs[kk][tx * 4 + j];
#pragma unroll
            for (int i = 0; i < 4; i++)
#pragma unroll
                for (int j = 0; j < 4; j++) acc[i][j] = fmaf(a[i], bv[j], acc[i][j]);
        }
        __syncthreads();
    }
    size_t base = (size_t)b * T_ * E_ + h * D_;
#pragma unroll
    for (int i = 0; i < 4; i++)
#pragma unroll
        for (int j = 0; j < 4; j++) {
            size_t off = base + (size_t)(r0 + ty * 4 + i) * E_ + tx * 4 + j;
            bf16 hh, ll; split2(acc[i][j], hh, ll);
            attnh[off] = hh; attnl[off] = ll;
        }
}

// ---------------------------------------------------------------------------
// Launch
// ---------------------------------------------------------------------------
extern "C" void kernel_launch(void* const* d_in, const int* in_sizes, int n_in,
                              void* d_out, int out_size) {
    const float* idx  = (const float*)d_in[0];
    const float* tok  = (const float*)d_in[1];
    const float* posW = (const float*)d_in[2];
    const float* posb = (const float*)d_in[3];
    const float* Wq   = (const float*)d_in[4];
    const float* Wk   = (const float*)d_in[5];
    const float* Wv   = (const float*)d_in[6];
    const float* Wo   = (const float*)d_in[7];
    const float* bo   = (const float*)d_in[8];
    const float* W1   = (const float*)d_in[9];
    const float* b1   = (const float*)d_in[10];
    const float* W2   = (const float*)d_in[11];
    const float* b2   = (const float*)d_in[12];
    const float* ln1g = (const float*)d_in[13];
    const float* ln1b = (const float*)d_in[14];
    const float* ln2g = (const float*)d_in[15];
    const float* ln2b = (const float*)d_in[16];
    const float* lnfg = (const float*)d_in[17];
    const float* lnfb = (const float*)d_in[18];
    const float* lmW  = (const float*)d_in[19];
    const float* lmb  = (const float*)d_in[20];
    float* out = (float*)d_out;

    float *x, *q, *k, *v, *s;
    bf16 *hh, *hl, *ath, *atl, *mh, *ml;
    bf16 *wqh, *wql, *wkh, *wkl, *wvh, *wvl, *woh, *wol, *w1h, *w1l, *w2h, *w2l, *lmh, *lml;
    cudaGetSymbolAddress((void**)&x,   g_x);
    cudaGetSymbolAddress((void**)&q,   g_q);
    cudaGetSymbolAddress((void**)&k,   g_k);
    cudaGetSymbolAddress((void**)&v,   g_v);
    cudaGetSymbolAddress((void**)&s,   g_s);
    cudaGetSymbolAddress((void**)&hh,  g_h_h);
    cudaGetSymbolAddress((void**)&hl,  g_h_l);
    cudaGetSymbolAddress((void**)&ath, g_attn_h);
    cudaGetSymbolAddress((void**)&atl, g_attn_l);
    cudaGetSymbolAddress((void**)&mh,  g_mlp_h);
    cudaGetSymbolAddress((void**)&ml,  g_mlp_l);
    cudaGetSymbolAddress((void**)&wqh, g_wq_h); cudaGetSymbolAddress((void**)&wql, g_wq_l);
    cudaGetSymbolAddress((void**)&wkh, g_wk_h); cudaGetSymbolAddress((void**)&wkl, g_wk_l);
    cudaGetSymbolAddress((void**)&wvh, g_wv_h); cudaGetSymbolAddress((void**)&wvl, g_wv_l);
    cudaGetSymbolAddress((void**)&woh, g_wo_h); cudaGetSymbolAddress((void**)&wol, g_wo_l);
    cudaGetSymbolAddress((void**)&w1h, g_w1_h); cudaGetSymbolAddress((void**)&w1l, g_w1_l);
    cudaGetSymbolAddress((void**)&w2h, g_w2_h); cudaGetSymbolAddress((void**)&w2l, g_w2_l);
    cudaGetSymbolAddress((void**)&lmh, g_lm_h); cudaGetSymbolAddress((void**)&lml, g_lm_l);

    dim3 tb(32, 8);
    dim3 gEEt(E_ / 32, E_ / 32);     // 1024x1024
    dim3 gW1t(FF / 32, E_ / 32);     // K=E, N=FF
    dim3 gW2t(E_ / 32, FF / 32);     // K=FF, N=E
    dim3 gLMt(V_ / 32, E_ / 32);     // K=E, N=800
    for (int l = 0; l < L_; l++) {
        size_t oEE = (size_t)l * E_ * E_;
        size_t oEF = (size_t)l * E_ * FF;
        tsplit_kernel<<<gEEt, tb>>>(Wq + oEE, wqh + oEE, wql + oEE, E_, E_);
        tsplit_kernel<<<gEEt, tb>>>(Wk + oEE, wkh + oEE, wkl + oEE, E_, E_);
        tsplit_kernel<<<gEEt, tb>>>(Wv + oEE, wvh + oEE, wvl + oEE, E_, E_);
        tsplit_kernel<<<gEEt, tb>>>(Wo + oEE, woh + oEE, wol + oEE, E_, E_);
        tsplit_kernel<<<gW1t, tb>>>(W1 + oEF, w1h + oEF, w1l + oEF, E_, FF);
        tsplit_kernel<<<gW2t, tb>>>(W2 + oEF, w2h + oEF, w2l + oEF, FF, E_);
    }
    tsplit_kernel<<<gLMt, tb>>>(lmW, lmh, lml, E_, V_);

    embed_kernel<<<MTOK, 256>>>(idx, tok, posW, posb, x);

    dim3 gEE(E_ / 128, MTOK / 128);          // (8,16)
    dim3 gEF(FF / 128, MTOK / 128);          // (32,16)
    dim3 gVg((V_ + 127) / 128, MTOK / 128);  // (7,16)
    dim3 gS(T_ / 64, T_ / 64, B_ * H_);
    dim3 gPV(1, T_ / 64, B_ * H_);

    for (int l = 0; l < L_; l++) {
        size_t oEE = (size_t)l * E_ * E_;
        size_t oEF = (size_t)l * E_ * FF;
        ln_split_kernel<<<MTOK, 256>>>(x, ln1g + l * E_, ln1b + l * E_, hh, hl);
        mma_gemm<0, 0, 0><<<gEE, 256>>>(hh, hl, wqh + oEE, wql + oEE,
                                        nullptr, nullptr, q, nullptr, nullptr, MTOK, E_, E_);
        mma_gemm<0, 0, 0><<<gEE, 256>>>(hh, hl, wkh + oEE, wkl + oEE,
                                        nullptr, nullptr, k, nullptr, nullptr, MTOK, E_, E_);
        mma_gemm<0, 0, 0><<<gEE, 256>>>(hh, hl, wvh + oEE, wvl + oEE,
                                        nullptr, nullptr, v, nullptr, nullptr, MTOK, E_, E_);
        scores_kernel<<<gS, 256>>>(q, k, s);
        softmax_kernel<<<B_ * H_ * T_, 256>>>(s);
        pv_kernel<<<gPV, 256>>>(s, v, ath, atl);
        mma_gemm<0, 0, 0><<<gEE, 256>>>(ath, atl, woh + oEE, wol + oEE,
                                        bo + l * E_, x, x, nullptr, nullptr, MTOK, E_, E_);
        ln_split_kernel<<<MTOK, 256>>>(x, ln2g + l * E_, ln2b + l * E_, hh, hl);
        mma_gemm<1, 1, 0><<<gEF, 256>>>(hh, hl, w1h + oEF, w1l + oEF,
                                        b1 + l * FF, nullptr, nullptr, mh, ml, MTOK, FF, E_);
        mma_gemm<0, 0, 0><<<gEE, 256>>>(mh, ml, w2h + oEF, w2l + oEF,
                                        b2 + l * E_, x, x, nullptr, nullptr, MTOK, E_, FF);
    }
    ln_split_kernel<<<MTOK, 256>>>(x, lnfg, lnfb, hh, hl);
    mma_gemm<0, 0, 1><<<gVg, 256>>>(hh, hl, lmh, lml,
                                    lmb, nullptr, out, nullptr, nullptr, MTOK, V_, E_);
}

// round 7
// speedup vs baseline: 1.7673x; 1.1297x over previous
#include <cuda_runtime.h>
#include <cuda_bf16.h>
#include <math.h>
#include <stdint.h>

// Problem constants
#define L_    8
#define H_    16
#define E_    1024
#define T_    1024
#define B_    2
#define V_    800
#define D_    64
#define MTOK  2048      // B*T
#define FF    4096      // 4*E

typedef __nv_bfloat16 bf16;

// ---------------------------------------------------------------------------
// Scratch (device globals: allocation-free per harness rules)
// ---------------------------------------------------------------------------
__device__ float g_x[MTOK * E_];                   // residual stream (fp32)
__device__ float g_q[MTOK * E_];
__device__ float g_k[MTOK * E_];
__device__ float g_v[MTOK * E_];
__device__ float g_s[(size_t)B_ * H_ * T_ * T_];   // 128 MB score matrix

// split-bf16 activations
__device__ bf16 g_h_h[MTOK * E_];
__device__ bf16 g_h_l[MTOK * E_];
__device__ bf16 g_attn_h[MTOK * E_];
__device__ bf16 g_attn_l[MTOK * E_];
__device__ bf16 g_mlp_h[(size_t)MTOK * FF];
__device__ bf16 g_mlp_l[(size_t)MTOK * FF];

// split + transposed weights  ([N][K] row-major)
__device__ bf16 g_wq_h[(size_t)L_ * E_ * E_];
__device__ bf16 g_wq_l[(size_t)L_ * E_ * E_];
__device__ bf16 g_wk_h[(size_t)L_ * E_ * E_];
__device__ bf16 g_wk_l[(size_t)L_ * E_ * E_];
__device__ bf16 g_wv_h[(size_t)L_ * E_ * E_];
__device__ bf16 g_wv_l[(size_t)L_ * E_ * E_];
__device__ bf16 g_wo_h[(size_t)L_ * E_ * E_];
__device__ bf16 g_wo_l[(size_t)L_ * E_ * E_];
__device__ bf16 g_w1_h[(size_t)L_ * E_ * FF];
__device__ bf16 g_w1_l[(size_t)L_ * E_ * FF];
__device__ bf16 g_w2_h[(size_t)L_ * E_ * FF];
__device__ bf16 g_w2_l[(size_t)L_ * E_ * FF];
__device__ bf16 g_lm_h[(size_t)E_ * V_];
__device__ bf16 g_lm_l[(size_t)E_ * V_];

__device__ __forceinline__ float neg_inf() { return __int_as_float(0xff800000); }

__device__ __forceinline__ void split2(float v, bf16& h, bf16& l) {
    h = __float2bfloat16_rn(v);
    l = __float2bfloat16_rn(v - __bfloat162float(h));
}

// ---------------------------------------------------------------------------
// Transpose + split: W[K][N] fp32 -> Th/Tl [N][K] bf16, batched over layers (z)
// ---------------------------------------------------------------------------
__global__ void tsplit_kernel(const float* __restrict__ W,
                              bf16* __restrict__ Th, bf16* __restrict__ Tl,
                              int K, int N, size_t zstride) {
    const float* Wz = W + (size_t)blockIdx.z * zstride;
    bf16* Thz = Th + (size_t)blockIdx.z * zstride;
    bf16* Tlz = Tl + (size_t)blockIdx.z * zstride;
    __shared__ float t[32][33];
    int n0 = blockIdx.x * 32, k0 = blockIdx.y * 32;
    int tx = threadIdx.x, ty = threadIdx.y;   // 32 x 8
#pragma unroll
    for (int r = 0; r < 4; r++)
        t[ty + r * 8][tx] = Wz[(size_t)(k0 + ty + r * 8) * N + n0 + tx];
    __syncthreads();
#pragma unroll
    for (int r = 0; r < 4; r++) {
        int n = n0 + ty + r * 8;
        int k = k0 + tx;
        float v = t[tx][ty + r * 8];
        bf16 h, l; split2(v, h, l);
        Thz[(size_t)n * K + k] = h;
        Tlz[(size_t)n * K + k] = l;
    }
}

// ---------------------------------------------------------------------------
// Embedding (fp32 residual)
// ---------------------------------------------------------------------------
__global__ void embed_kernel(const float* __restrict__ idx,
                             const float* __restrict__ tok_table,
                             const float* __restrict__ posW,
                             const float* __restrict__ posb,
                             float* __restrict__ x) {
    int row = blockIdx.x;
    float lat = idx[row * 3 + 0];
    float lon = idx[row * 3 + 1];
    float wl  = idx[row * 3 + 2];
    float f = rintf(wl * 100.0f - 300.0f);
    f = fminf(fmaxf(f, 0.0f), (float)(V_ - 1));
    int tok = (int)f;
    const float* te = tok_table + (size_t)tok * E_;
    for (int e = threadIdx.x; e < E_; e += blockDim.x)
        x[(size_t)row * E_ + e] = te[e] + lat * posW[e] + lon * posW[E_ + e] + posb[e];
}

// ---------------------------------------------------------------------------
// LayerNorm -> split-bf16 output
// ---------------------------------------------------------------------------
__global__ void ln_split_kernel(const float* __restrict__ in,
                                const float* __restrict__ g,
                                const float* __restrict__ b,
                                bf16* __restrict__ oh, bf16* __restrict__ ol) {
    int row = blockIdx.x;
    int tid = threadIdx.x;
    const float* px = in + (size_t)row * E_;
    float vals[4];
    float s = 0.f, sq = 0.f;
#pragma unroll
    for (int i = 0; i < 4; i++) {
        float v = px[tid + i * 256];
        vals[i] = v; s += v; sq += v * v;
    }
    __shared__ float r1[256], r2[256];
    r1[tid] = s; r2[tid] = sq;
    __syncthreads();
    for (int o = 128; o > 0; o >>= 1) {
        if (tid < o) { r1[tid] += r1[tid + o]; r2[tid] += r2[tid + o]; }
        __syncthreads();
    }
    float mean = r1[0] * (1.0f / E_);
    float var  = r2[0] * (1.0f / E_) - mean * mean;
    float rstd = rsqrtf(var + 1e-5f);
#pragma unroll
    for (int i = 0; i < 4; i++) {
        int e = tid + i * 256;
        float v = (vals[i] - mean) * rstd * g[e] + b[e];
        bf16 h, l; split2(v, h, l);
        oh[(size_t)row * E_ + e] = h;
        ol[(size_t)row * E_ + e] = l;
    }
}

// ---------------------------------------------------------------------------
// Split-precision bf16 tensor-core GEMM (ldmatrix + cp.async 3-stage)
//   C[M,N] = act( (Ah+Al)[M,K] @ (Bh+Bl)[N,K]^T + bias + Cin )
//   via Ah@Bh + Ah@Bl + Al@Bh   (mma.m16n8k16, fp32 accum)
// BM=128 BN=128 BK=32, 256 threads, warp grid 2x4, warp tile 64x32.
// Smem per stage: 4 arrays x [128 rows][40 bf16] (pad 40 -> conflict-free).
// blockIdx.z selects among up to 3 weight/output sets (QKV fusion).
// ---------------------------------------------------------------------------
struct TriW {
    const bf16* bh[3];
    const bf16* bl[3];
    float*      out[3];
};

#define SMEM_STAGE_ELEMS 20480      // 4 * 128 * 40
#define SMEM_ARR_ELEMS   5120       // 128 * 40
#define GEMM_SMEM_BYTES  (3 * SMEM_STAGE_ELEMS * 2)

#define MMA_BF16(c, a, b0v, b1v)                                              \
    asm volatile(                                                             \
        "mma.sync.aligned.m16n8k16.row.col.f32.bf16.bf16.f32 "                \
        "{%0,%1,%2,%3}, {%4,%5,%6,%7}, {%8,%9}, {%0,%1,%2,%3};\n"             \
        : "+f"((c)[0]), "+f"((c)[1]), "+f"((c)[2]), "+f"((c)[3])              \
        : "r"((a)[0]), "r"((a)[1]), "r"((a)[2]), "r"((a)[3]),                 \
          "r"(b0v), "r"(b1v))

#define LDSM4(r0, r1, r2, r3, addr)                                           \
    asm volatile("ldmatrix.sync.aligned.m8n8.x4.shared.b16 {%0,%1,%2,%3}, [%4];" \
        : "=r"(r0), "=r"(r1), "=r"(r2), "=r"(r3) : "r"(addr))

__device__ __forceinline__ void cp16(uint32_t dst, const void* src) {
    asm volatile("cp.async.cg.shared.global [%0], [%1], 16;\n" :: "r"(dst), "l"(src));
}
__device__ __forceinline__ void cp_commit() {
    asm volatile("cp.async.commit_group;\n");
}
__device__ __forceinline__ void cp_wait2() {
    asm volatile("cp.async.wait_group 2;\n");
}

template <int NGUARD>
__device__ __forceinline__ void issue_stage(
    uint32_t smem_u32, int stage, int kt,
    const bf16* __restrict__ gAh, const bf16* __restrict__ gAl,
    const bf16* __restrict__ gBh, const bf16* __restrict__ gBl,
    int K, int limB, int tid) {
    int row = tid >> 2;          // 0..63
    int c   = tid & 3;           // 16B chunk within 64B
    int koff = kt * 32 + c * 8;
    uint32_t base = smem_u32 + (uint32_t)stage * (SMEM_STAGE_ELEMS * 2);
#pragma unroll
    for (int hfl = 0; hfl < 2; hfl++) {
        int r = row + hfl * 64;
        uint32_t doff = (uint32_t)(r * 40 + c * 8) * 2;
        cp16(base + 0 * (SMEM_ARR_ELEMS * 2) + doff, gAh + (size_t)r * K + koff);
        cp16(base + 1 * (SMEM_ARR_ELEMS * 2) + doff, gAl + (size_t)r * K + koff);
        int rb = NGUARD ? ((r < limB) ? r : 0) : r;
        cp16(base + 2 * (SMEM_ARR_ELEMS * 2) + doff, gBh + (size_t)rb * K + koff);
        cp16(base + 3 * (SMEM_ARR_ELEMS * 2) + doff, gBl + (size_t)rb * K + koff);
    }
}

template <int RELU, int SPLIT_OUT, int NGUARD>
__global__ void __launch_bounds__(256) mma_gemm(
    const bf16* __restrict__ Ah, const bf16* __restrict__ Al,
    TriW tw,
    const float* __restrict__ bias, const float* __restrict__ Cin,
    bf16* __restrict__ Ch, bf16* __restrict__ Cl,
    int M, int N, int K) {
    extern __shared__ bf16 smbuf[];
    const uint32_t smem_u32 = (uint32_t)__cvta_generic_to_shared(smbuf);

    const int z = blockIdx.z;
    const bf16* __restrict__ Bh = tw.bh[z];
    const bf16* __restrict__ Bl = tw.bl[z];
    float* __restrict__ Cf = tw.out[z];

    const int tid  = threadIdx.x;
    const int lane = tid & 31;
    const int warp = tid >> 5;
    const int wm = warp >> 2;            // 0..1
    const int wn = warp & 3;             // 0..3
    const int l15 = lane & 15;
    const int lhi = lane >> 4;           // 0/1
    const int gid = lane >> 2, t4 = lane & 3;
    const int m0 = blockIdx.y * 128, n0 = blockIdx.x * 128;

    const bf16* gAh = Ah + (size_t)m0 * K;
    const bf16* gAl = Al + (size_t)m0 * K;
    const bf16* gBh = Bh + (size_t)n0 * K;
    const bf16* gBl = Bl + (size_t)n0 * K;
    const int limB = N - n0;

    float acc[4][4][4];
#pragma unroll
    for (int i = 0; i < 4; i++)
#pragma unroll
        for (int j = 0; j < 4; j++)
#pragma unroll
            for (int e = 0; e < 4; e++) acc[i][j][e] = 0.f;

    const int nk = K >> 5;   // K / 32

    issue_stage<NGUARD>(smem_u32, 0, 0, gAh, gAl, gBh, gBl, K, limB, tid);
    cp_commit();
    issue_stage<NGUARD>(smem_u32, 1, 1, gAh, gAl, gBh, gBl, K, limB, tid);
    cp_commit();

    for (int kt = 0; kt < nk; kt++) {
        if (kt + 2 < nk)
            issue_stage<NGUARD>(smem_u32, (kt + 2) % 3, kt + 2,
                                gAh, gAl, gBh, gBl, K, limB, tid);
        cp_commit();
        cp_wait2();
        __syncthreads();

        const uint32_t stageB = smem_u32 + (uint32_t)(kt % 3) * (SMEM_STAGE_ELEMS * 2);
#pragma unroll
        for (int ks = 0; ks < 2; ks++) {
            uint32_t afh[4][4], afl[4][4], bfh[2][4], bfl[2][4];
#pragma unroll
            for (int i = 0; i < 4; i++) {
                uint32_t ra = stageB +
                    (uint32_t)((wm * 64 + i * 16 + l15) * 40 + ks * 16 + lhi * 8) * 2;
                LDSM4(afh[i][0], afh[i][1], afh[i][2], afh[i][3], ra);
                LDSM4(afl[i][0], afl[i][1], afl[i][2], afl[i][3],
                      ra + (SMEM_ARR_ELEMS * 2));
            }
#pragma unroll
            for (int jj = 0; jj < 2; jj++) {
                uint32_t rb = stageB + 2 * (SMEM_ARR_ELEMS * 2) +
                    (uint32_t)((wn * 32 + jj * 16 + l15) * 40 + ks * 16 + lhi * 8) * 2;
                LDSM4(bfh[jj][0], bfh[jj][1], bfh[jj][2], bfh[jj][3], rb);
                LDSM4(bfl[jj][0], bfl[jj][1], bfl[jj][2], bfl[jj][3],
                      rb + (SMEM_ARR_ELEMS * 2));
            }
#pragma unroll
            for (int j = 0; j < 4; j++) {
                const int jj = j >> 1, sel = j & 1;
                const uint32_t b0h = bfh[jj][sel], b1h = bfh[jj][sel + 2];
                const uint32_t b0l = bfl[jj][sel], b1l = bfl[jj][sel + 2];
#pragma unroll
                for (int i = 0; i < 4; i++) MMA_BF16(acc[i][j], afh[i], b0h, b1h);
#pragma unroll
                for (int i = 0; i < 4; i++) MMA_BF16(acc[i][j], afh[i], b0l, b1l);
#pragma unroll
                for (int i = 0; i < 4; i++) MMA_BF16(acc[i][j], afl[i], b0h, b1h);
            }
        }
        __syncthreads();
    }

    // epilogue: two fp32 (or bf16x2) per store, cols 2*t4, 2*t4+1
#pragma unroll
    for (int i = 0; i < 4; i++) {
#pragma unroll
        for (int j = 0; j < 4; j++) {
            const int colb = n0 + wn * 32 + j * 8 + 2 * t4;
            if (NGUARD && colb >= N) continue;
#pragma unroll
            for (int half = 0; half < 2; half++) {
                const int row = m0 + wm * 64 + i * 16 + gid + half * 8;
                float v0 = acc[i][j][half * 2 + 0];
                float v1 = acc[i][j][half * 2 + 1];
                if (bias) { v0 += bias[colb]; v1 += bias[colb + 1]; }
                if (Cin) {
                    float2 ci = *(const float2*)&Cin[(size_t)row * N + colb];
                    v0 += ci.x; v1 += ci.y;
                }
                if (RELU) { v0 = fmaxf(v0, 0.f); v1 = fmaxf(v1, 0.f); }
                if (SPLIT_OUT) {
                    bf16 h0, l0, h1, l1;
                    split2(v0, h0, l0); split2(v1, h1, l1);
                    __nv_bfloat162 ph; ph.x = h0; ph.y = h1;
                    __nv_bfloat162 pl; pl.x = l0; pl.y = l1;
                    *(__nv_bfloat162*)&Ch[(size_t)row * N + colb] = ph;
                    *(__nv_bfloat162*)&Cl[(size_t)row * N + colb] = pl;
                } else {
                    float2 o; o.x = v0; o.y = v1;
                    *(float2*)&Cf[(size_t)row * N + colb] = o;
                }
            }
        }
    }
}

// ---------------------------------------------------------------------------
// Causal scores (fp32)
// ---------------------------------------------------------------------------
__global__ void __launch_bounds__(256) scores_kernel(
    const float* __restrict__ q, const float* __restrict__ k,
    float* __restrict__ s) {
    int bh = blockIdx.z;
    int b = bh >> 4, h = bh & 15;
    int r0 = blockIdx.y * 64;
    int c0 = blockIdx.x * 64;
    float* Sp = s + (size_t)bh * T_ * T_;
    int tid = threadIdx.x;

    if (c0 > r0 + 63) {
        float ni = neg_inf();
#pragma unroll
        for (int p = 0; p < 16; p++) {
            int idx = tid + p * 256;
            int rr = idx >> 6, cc = idx & 63;
            Sp[(size_t)(r0 + rr) * T_ + c0 + cc] = ni;
        }
        return;
    }

    __shared__ float Qs[64][65];
    __shared__ float Ks[64][65];
    const float* Qb = q + ((size_t)b * T_ + r0) * E_ + h * D_;
    const float* Kb = k + ((size_t)b * T_ + c0) * E_ + h * D_;
#pragma unroll
    for (int p = 0; p < 4; p++) {
        int idx = tid + p * 256;
        int rr = idx >> 4;
        int c4 = (idx & 15) * 4;
        float4 qa = *(const float4*)(Qb + (size_t)rr * E_ + c4);
        Qs[rr][c4] = qa.x; Qs[rr][c4 + 1] = qa.y; Qs[rr][c4 + 2] = qa.z; Qs[rr][c4 + 3] = qa.w;
        float4 ka = *(const float4*)(Kb + (size_t)rr * E_ + c4);
        Ks[rr][c4] = ka.x; Ks[rr][c4 + 1] = ka.y; Ks[rr][c4 + 2] = ka.z; Ks[rr][c4 + 3] = ka.w;
    }
    __syncthreads();

    int tx = tid & 15, ty = tid >> 4;
    float acc[4][4];
#pragma unroll
    for (int i = 0; i < 4; i++)
#pragma unroll
        for (int j = 0; j < 4; j++) acc[i][j] = 0.f;
#pragma unroll 8
    for (int kk = 0; kk < 64; kk++) {
        float a[4], bv[4];
#pragma unroll
        for (int i = 0; i < 4; i++) a[i] = Qs[ty * 4 + i][kk];
#pragma unroll
        for (int j = 0; j < 4; j++) bv[j] = Ks[tx * 4 + j][kk];
#pragma unroll
        for (int i = 0; i < 4; i++)
#pragma unroll
            for (int j = 0; j < 4; j++) acc[i][j] = fmaf(a[i], bv[j], acc[i][j]);
    }
    const float scale = 0.125f;
    float ni = neg_inf();
#pragma unroll
    for (int i = 0; i < 4; i++) {
        int rr = r0 + ty * 4 + i;
#pragma unroll
        for (int j = 0; j < 4; j++) {
            int cc = c0 + tx * 4 + j;
            Sp[(size_t)rr * T_ + cc] = (cc <= rr) ? acc[i][j] * scale : ni;
        }
    }
}

// ---------------------------------------------------------------------------
// Row softmax
// ---------------------------------------------------------------------------
__global__ void softmax_kernel(float* __restrict__ s) {
    size_t row = blockIdx.x;
    float* p = s + row * (size_t)T_;
    int tid = threadIdx.x;
    float v[4];
    float mx = neg_inf();
#pragma unroll
    for (int i = 0; i < 4; i++) {
        v[i] = p[tid + i * 256];
        mx = fmaxf(mx, v[i]);
    }
    __shared__ float red[256];
    red[tid] = mx;
    __syncthreads();
    for (int o = 128; o > 0; o >>= 1) {
        if (tid < o) red[tid] = fmaxf(red[tid], red[tid + o]);
        __syncthreads();
    }
    mx = red[0];
    __syncthreads();
    float sum = 0.f;
#pragma unroll
    for (int i = 0; i < 4; i++) {
        v[i] = expf(v[i] - mx);
        sum += v[i];
    }
    red[tid] = sum;
    __syncthreads();
    for (int o = 128; o > 0; o >>= 1) {
        if (tid < o) red[tid] += red[tid + o];
        __syncthreads();
    }
    float inv = 1.0f / red[0];
#pragma unroll
    for (int i = 0; i < 4; i++) p[tid + i * 256] = v[i] * inv;
}

// ---------------------------------------------------------------------------
// P@V -> split-bf16 attn output
// ---------------------------------------------------------------------------
__global__ void __launch_bounds__(256) pv_kernel(
    const float* __restrict__ s, const float* __restrict__ v,
    bf16* __restrict__ attnh, bf16* __restrict__ attnl) {
    int bh = blockIdx.z;
    int b = bh >> 4, h = bh & 15;
    int r0 = blockIdx.y * 64;
    const float* Sp = s + (size_t)bh * T_ * T_;
    const float* Vb = v + (size_t)b * T_ * E_ + h * D_;
    __shared__ float As[16][65];
    __shared__ float Bs[16][68];
    int tid = threadIdx.x;
    int tx = tid & 15, ty = tid >> 4;
    float acc[4][4];
#pragma unroll
    for (int i = 0; i < 4; i++)
#pragma unroll
        for (int j = 0; j < 4; j++) acc[i][j] = 0.f;

    int kend = r0 + 64;
    for (int k0 = 0; k0 < kend; k0 += 16) {
        {
            int m = tid >> 2;
            int k4 = (tid & 3) * 4;
            float4 a4 = *(const float4*)(Sp + (size_t)(r0 + m) * T_ + k0 + k4);
            As[k4 + 0][m] = a4.x; As[k4 + 1][m] = a4.y;
            As[k4 + 2][m] = a4.z; As[k4 + 3][m] = a4.w;
        }
        {
            int kk = tid >> 4;
            int n4 = (tid & 15) * 4;
            float4 b4 = *(const float4*)(Vb + (size_t)(k0 + kk) * E_ + n4);
            *(float4*)&Bs[kk][n4] = b4;
        }
        __syncthreads();
#pragma unroll
        for (int kk = 0; kk < 16; kk++) {
            float a[4], bv[4];
#pragma unroll
            for (int i = 0; i < 4; i++) a[i] = As[kk][ty * 4 + i];
#pragma unroll
            for (int j = 0; j < 4; j++) bv[j] = Bs[kk][tx * 4 + j];
#pragma unroll
            for (int i = 0; i < 4; i++)
#pragma unroll
                for (int j = 0; j < 4; j++) acc[i][j] = fmaf(a[i], bv[j], acc[i][j]);
        }
        __syncthreads();
    }
    size_t base = (size_t)b * T_ * E_ + h * D_;
#pragma unroll
    for (int i = 0; i < 4; i++)
#pragma unroll
        for (int j = 0; j < 4; j++) {
            size_t off = base + (size_t)(r0 + ty * 4 + i) * E_ + tx * 4 + j;
            bf16 hh, ll; split2(acc[i][j], hh, ll);
            attnh[off] = hh; attnl[off] = ll;
        }
}

// ---------------------------------------------------------------------------
// Launch
// ---------------------------------------------------------------------------
extern "C" void kernel_launch(void* const* d_in, const int* in_sizes, int n_in,
                              void* d_out, int out_size) {
    const float* idx  = (const float*)d_in[0];
    const float* tok  = (const float*)d_in[1];
    const float* posW = (const float*)d_in[2];
    const float* posb = (const float*)d_in[3];
    const float* Wq   = (const float*)d_in[4];
    const float* Wk   = (const float*)d_in[5];
    const float* Wv   = (const float*)d_in[6];
    const float* Wo   = (const float*)d_in[7];
    const float* bo   = (const float*)d_in[8];
    const float* W1   = (const float*)d_in[9];
    const float* b1   = (const float*)d_in[10];
    const float* W2   = (const float*)d_in[11];
    const float* b2   = (const float*)d_in[12];
    const float* ln1g = (const float*)d_in[13];
    const float* ln1b = (const float*)d_in[14];
    const float* ln2g = (const float*)d_in[15];
    const float* ln2b = (const float*)d_in[16];
    const float* lnfg = (const float*)d_in[17];
    const float* lnfb = (const float*)d_in[18];
    const float* lmW  = (const float*)d_in[19];
    const float* lmb  = (const float*)d_in[20];
    float* out = (float*)d_out;

    float *x, *q, *k, *v, *s;
    bf16 *hh, *hl, *ath, *atl, *mh, *ml;
    bf16 *wqh, *wql, *wkh, *wkl, *wvh, *wvl, *woh, *wol, *w1h, *w1l, *w2h, *w2l, *lmh, *lml;
    cudaGetSymbolAddress((void**)&x,   g_x);
    cudaGetSymbolAddress((void**)&q,   g_q);
    cudaGetSymbolAddress((void**)&k,   g_k);
    cudaGetSymbolAddress((void**)&v,   g_v);
    cudaGetSymbolAddress((void**)&s,   g_s);
    cudaGetSymbolAddress((void**)&hh,  g_h_h);
    cudaGetSymbolAddress((void**)&hl,  g_h_l);
    cudaGetSymbolAddress((void**)&ath, g_attn_h);
    cudaGetSymbolAddress((void**)&atl, g_attn_l);
    cudaGetSymbolAddress((void**)&mh,  g_mlp_h);
    cudaGetSymbolAddress((void**)&ml,  g_mlp_l);
    cudaGetSymbolAddress((void**)&wqh, g_wq_h); cudaGetSymbolAddress((void**)&wql, g_wq_l);
    cudaGetSymbolAddress((void**)&wkh, g_wk_h); cudaGetSymbolAddress((void**)&wkl, g_wk_l);
    cudaGetSymbolAddress((void**)&wvh, g_wv_h); cudaGetSymbolAddress((void**)&wvl, g_wv_l);
    cudaGetSymbolAddress((void**)&woh, g_wo_h); cudaGetSymbolAddress((void**)&wol, g_wo_l);
    cudaGetSymbolAddress((void**)&w1h, g_w1_h); cudaGetSymbolAddress((void**)&w1l, g_w1_l);
    cudaGetSymbolAddress((void**)&w2h, g_w2_h); cudaGetSymbolAddress((void**)&w2l, g_w2_l);
    cudaGetSymbolAddress((void**)&lmh, g_lm_h); cudaGetSymbolAddress((void**)&lml, g_lm_l);

    // raise dynamic smem limits (idempotent; host-side, capture-safe)
    cudaFuncSetAttribute(mma_gemm<0, 0, 0>,
                         cudaFuncAttributeMaxDynamicSharedMemorySize, GEMM_SMEM_BYTES);
    cudaFuncSetAttribute(mma_gemm<1, 1, 0>,
                         cudaFuncAttributeMaxDynamicSharedMemorySize, GEMM_SMEM_BYTES);
    cudaFuncSetAttribute(mma_gemm<0, 0, 1>,
                         cudaFuncAttributeMaxDynamicSharedMemorySize, GEMM_SMEM_BYTES);

    // weight transpose+split, batched over layers
    dim3 tb(32, 8);
    tsplit_kernel<<<dim3(E_ / 32, E_ / 32, L_), tb>>>(Wq, wqh, wql, E_, E_, (size_t)E_ * E_);
    tsplit_kernel<<<dim3(E_ / 32, E_ / 32, L_), tb>>>(Wk, wkh, wkl, E_, E_, (size_t)E_ * E_);
    tsplit_kernel<<<dim3(E_ / 32, E_ / 32, L_), tb>>>(Wv, wvh, wvl, E_, E_, (size_t)E_ * E_);
    tsplit_kernel<<<dim3(E_ / 32, E_ / 32, L_), tb>>>(Wo, woh, wol, E_, E_, (size_t)E_ * E_);
    tsplit_kernel<<<dim3(FF / 32, E_ / 32, L_), tb>>>(W1, w1h, w1l, E_, FF, (size_t)E_ * FF);
    tsplit_kernel<<<dim3(E_ / 32, FF / 32, L_), tb>>>(W2, w2h, w2l, FF, E_, (size_t)E_ * FF);
    tsplit_kernel<<<dim3(V_ / 32, E_ / 32, 1), tb>>>(lmW, lmh, lml, E_, V_, 0);

    embed_kernel<<<MTOK, 256>>>(idx, tok, posW, posb, x);

    dim3 gQKV(E_ / 128, MTOK / 128, 3);       // (8,16,3)
    dim3 gEE(E_ / 128, MTOK / 128, 1);        // (8,16)
    dim3 gEF(FF / 128, MTOK / 128, 1);        // (32,16)
    dim3 gVg((V_ + 127) / 128, MTOK / 128, 1);// (7,16)
    dim3 gS(T_ / 64, T_ / 64, B_ * H_);
    dim3 gPV(1, T_ / 64, B_ * H_);

    for (int l = 0; l < L_; l++) {
        size_t oEE = (size_t)l * E_ * E_;
        size_t oEF = (size_t)l * E_ * FF;

        ln_split_kernel<<<MTOK, 256>>>(x, ln1g + l * E_, ln1b + l * E_, hh, hl);

        TriW qkv;
        qkv.bh[0] = wqh + oEE; qkv.bl[0] = wql + oEE; qkv.out[0] = q;
        qkv.bh[1] = wkh + oEE; qkv.bl[1] = wkl + oEE; qkv.out[1] = k;
        qkv.bh[2] = wvh + oEE; qkv.bl[2] = wvl + oEE; qkv.out[2] = v;
        mma_gemm<0, 0, 0><<<gQKV, 256, GEMM_SMEM_BYTES>>>(
            hh, hl, qkv, nullptr, nullptr, nullptr, nullptr, MTOK, E_, E_);

        scores_kernel<<<gS, 256>>>(q, k, s);
        softmax_kernel<<<B_ * H_ * T_, 256>>>(s);
        pv_kernel<<<gPV, 256>>>(s, v, ath, atl);

        TriW wo; wo.bh[0] = woh + oEE; wo.bl[0] = wol + oEE; wo.out[0] = x;
        wo.bh[1] = wo.bh[0]; wo.bl[1] = wo.bl[0]; wo.out[1] = x;
        wo.bh[2] = wo.bh[0]; wo.bl[2] = wo.bl[0]; wo.out[2] = x;
        mma_gemm<0, 0, 0><<<gEE, 256, GEMM_SMEM_BYTES>>>(
            ath, atl, wo, bo + l * E_, x, nullptr, nullptr, MTOK, E_, E_);

        ln_split_kernel<<<MTOK, 256>>>(x, ln2g + l * E_, ln2b + l * E_, hh, hl);

        TriW w1; w1.bh[0] = w1h + oEF; w1.bl[0] = w1l + oEF; w1.out[0] = nullptr;
        w1.bh[1] = w1.bh[0]; w1.bl[1] = w1.bl[0]; w1.out[1] = nullptr;
        w1.bh[2] = w1.bh[0]; w1.bl[2] = w1.bl[0]; w1.out[2] = nullptr;
        mma_gemm<1, 1, 0><<<gEF, 256, GEMM_SMEM_BYTES>>>(
            hh, hl, w1, b1 + l * FF, nullptr, mh, ml, MTOK, FF, E_);

        TriW w2; w2.bh[0] = w2h + oEF; w2.bl[0] = w2l + oEF; w2.out[0] = x;
        w2.bh[1] = w2.bh[0]; w2.bl[1] = w2.bl[0]; w2.out[1] = x;
        w2.bh[2] = w2.bh[0]; w2.bl[2] = w2.bl[0]; w2.out[2] = x;
        mma_gemm<0, 0, 0><<<gEE, 256, GEMM_SMEM_BYTES>>>(
            mh, ml, w2, b2 + l * E_, x, nullptr, nullptr, MTOK, E_, FF);
    }
    ln_split_kernel<<<MTOK, 256>>>(x, lnfg, lnfb, hh, hl);

    TriW lm; lm.bh[0] = lmh; lm.bl[0] = lml; lm.out[0] = out;
    lm.bh[1] = lm.bh[0]; lm.bl[1] = lm.bl[0]; lm.out[1] = out;
    lm.bh[2] = lm.bh[0]; lm.bl[2] = lm.bl[0]; lm.out[2] = out;
    mma_gemm<0, 0, 1><<<gVg, 256, GEMM_SMEM_BYTES>>>(
        hh, hl, lm, lmb, nullptr, nullptr, nullptr, MTOK, V_, E_);
}

// round 12
// speedup vs baseline: 2.2984x; 1.3005x over previous
#include <cuda_runtime.h>
#include <cuda_bf16.h>
#include <math.h>
#include <stdint.h>
#include <string.h>

// Problem constants
#define L_    8
#define H_    16
#define E_    1024
#define T_    1024
#define B_    2
#define V_    800
#define D_    64
#define MTOK  2048      // B*T
#define FF    4096      // 4*E

typedef __nv_bfloat16 bf16;

// ---------------------------------------------------------------------------
// Scratch (device globals: allocation-free per harness rules)
// ---------------------------------------------------------------------------
__device__ float g_x[MTOK * E_];                   // residual stream (fp32)

// split-bf16 activations
__device__ bf16 g_h_h[MTOK * E_];
__device__ bf16 g_h_l[MTOK * E_];
__device__ bf16 g_q_h[MTOK * E_];
__device__ bf16 g_q_l[MTOK * E_];
__device__ bf16 g_k_h[MTOK * E_];
__device__ bf16 g_k_l[MTOK * E_];
__device__ bf16 g_vT_h[(size_t)E_ * MTOK];         // transposed V: [E][MTOK]
__device__ bf16 g_vT_l[(size_t)E_ * MTOK];
__device__ bf16 g_attn_h[MTOK * E_];
__device__ bf16 g_attn_l[MTOK * E_];
__device__ bf16 g_mlp_h[(size_t)MTOK * FF];
__device__ bf16 g_mlp_l[(size_t)MTOK * FF];

// split + transposed weights  ([N][K] row-major)
__device__ bf16 g_wq_h[(size_t)L_ * E_ * E_];
__device__ bf16 g_wq_l[(size_t)L_ * E_ * E_];
__device__ bf16 g_wk_h[(size_t)L_ * E_ * E_];
__device__ bf16 g_wk_l[(size_t)L_ * E_ * E_];
__device__ bf16 g_wv_h[(size_t)L_ * E_ * E_];
__device__ bf16 g_wv_l[(size_t)L_ * E_ * E_];
__device__ bf16 g_wo_h[(size_t)L_ * E_ * E_];
__device__ bf16 g_wo_l[(size_t)L_ * E_ * E_];
__device__ bf16 g_w1_h[(size_t)L_ * E_ * FF];
__device__ bf16 g_w1_l[(size_t)L_ * E_ * FF];
__device__ bf16 g_w2_h[(size_t)L_ * E_ * FF];
__device__ bf16 g_w2_l[(size_t)L_ * E_ * FF];
__device__ bf16 g_lm_h[(size_t)E_ * V_];
__device__ bf16 g_lm_l[(size_t)E_ * V_];

__device__ __forceinline__ void split2(float v, bf16& h, bf16& l) {
    h = __float2bfloat16_rn(v);
    l = __float2bfloat16_rn(v - __bfloat162float(h));
}

__device__ __forceinline__ uint32_t pk2(bf16 a, bf16 b) {
    __nv_bfloat162 t; t.x = a; t.y = b;
    uint32_t r; memcpy(&r, &t, 4); return r;
}

// fast 2^y for y <= 0 (clamped at -120): magic-number round + deg-5 poly
__device__ __forceinline__ float fexp2(float y) {
    y = fmaxf(y, -120.f);
    float t = y + 12582912.f;                    // round-to-nearest int
    int n = __float_as_int(t) - 0x4B400000;
    float f = y - (t - 12582912.f);              // f in [-0.5, 0.5]
    float p = 1.33335814645e-3f;
    p = fmaf(p, f, 9.61812910763e-3f);
    p = fmaf(p, f, 5.55041086648e-2f);
    p = fmaf(p, f, 2.40226506959e-1f);
    p = fmaf(p, f, 6.93147180560e-1f);
    p = fmaf(p, f, 1.0f);
    return __int_as_float(__float_as_int(p) + (n << 23));
}

// ---------------------------------------------------------------------------
// mma / ldmatrix / cp.async primitives (legacy path — proven on this target)
// ---------------------------------------------------------------------------
#define MMA_BF16(c, a, b0v, b1v)                                              \
    asm volatile(                                                             \
        "mma.sync.aligned.m16n8k16.row.col.f32.bf16.bf16.f32 "                \
        "{%0,%1,%2,%3}, {%4,%5,%6,%7}, {%8,%9}, {%0,%1,%2,%3};\n"             \
        : "+f"((c)[0]), "+f"((c)[1]), "+f"((c)[2]), "+f"((c)[3])              \
        : "r"((a)[0]), "r"((a)[1]), "r"((a)[2]), "r"((a)[3]),                 \
          "r"(b0v), "r"(b1v))

#define LDSM4(r0, r1, r2, r3, addr)                                           \
    asm volatile("ldmatrix.sync.aligned.m8n8.x4.shared.b16 {%0,%1,%2,%3}, [%4];" \
        : "=r"(r0), "=r"(r1), "=r"(r2), "=r"(r3) : "r"(addr))

__device__ __forceinline__ uint32_t smem_addr_u32(const void* p) {
    uint32_t a;
    asm("{ .reg .u64 t; cvta.to.shared.u64 t, %1; cvt.u32.u64 %0, t; }"
        : "=r"(a) : "l"(p));
    return a;
}
__device__ __forceinline__ void cp16(uint32_t dst, const void* src) {
    asm volatile("cp.async.cg.shared.global [%0], [%1], 16;\n" :: "r"(dst), "l"(src));
}
__device__ __forceinline__ void cp_commit() {
    asm volatile("cp.async.commit_group;\n");
}
__device__ __forceinline__ void cp_wait1() {
    asm volatile("cp.async.wait_group 1;\n");
}
__device__ __forceinline__ void cp_wait2() {
    asm volatile("cp.async.wait_group 2;\n");
}

// ---------------------------------------------------------------------------
// Transpose + split: W[K][N] fp32 -> Th/Tl [N][K] bf16, batched over layers (z)
// ---------------------------------------------------------------------------
__global__ void tsplit_kernel(const float* __restrict__ W,
                              bf16* __restrict__ Th, bf16* __restrict__ Tl,
                              int K, int N, size_t zstride) {
    const float* Wz = W + (size_t)blockIdx.z * zstride;
    bf16* Thz = Th + (size_t)blockIdx.z * zstride;
    bf16* Tlz = Tl + (size_t)blockIdx.z * zstride;
    __shared__ float t[32][33];
    int n0 = blockIdx.x * 32, k0 = blockIdx.y * 32;
    int tx = threadIdx.x, ty = threadIdx.y;   // 32 x 8
#pragma unroll
    for (int r = 0; r < 4; r++)
        t[ty + r * 8][tx] = Wz[(size_t)(k0 + ty + r * 8) * N + n0 + tx];
    __syncthreads();
#pragma unroll
    for (int r = 0; r < 4; r++) {
        int n = n0 + ty + r * 8;
        int k = k0 + tx;
        float v = t[tx][ty + r * 8];
        bf16 h, l; split2(v, h, l);
        Thz[(size_t)n * K + k] = h;
        Tlz[(size_t)n * K + k] = l;
    }
}

// ---------------------------------------------------------------------------
// Embedding (fp32 residual)
// ---------------------------------------------------------------------------
__global__ void embed_kernel(const float* __restrict__ idx,
                             const float* __restrict__ tok_table,
                             const float* __restrict__ posW,
                             const float* __restrict__ posb,
                             float* __restrict__ x) {
    int row = blockIdx.x;
    float lat = idx[row * 3 + 0];
    float lon = idx[row * 3 + 1];
    float wl  = idx[row * 3 + 2];
    float f = rintf(wl * 100.0f - 300.0f);
    f = fminf(fmaxf(f, 0.0f), (float)(V_ - 1));
    int tok = (int)f;
    const float* te = tok_table + (size_t)tok * E_;
    for (int e = threadIdx.x; e < E_; e += blockDim.x)
        x[(size_t)row * E_ + e] = te[e] + lat * posW[e] + lon * posW[E_ + e] + posb[e];
}

// ---------------------------------------------------------------------------
// LayerNorm -> split-bf16 output
// ---------------------------------------------------------------------------
__global__ void ln_split_kernel(const float* __restrict__ in,
                                const float* __restrict__ g,
                                const float* __restrict__ b,
                                bf16* __restrict__ oh, bf16* __restrict__ ol) {
    int row = blockIdx.x;
    int tid = threadIdx.x;
    const float* px = in + (size_t)row * E_;
    float vals[4];
    float s = 0.f, sq = 0.f;
#pragma unroll
    for (int i = 0; i < 4; i++) {
        float v = px[tid + i * 256];
        vals[i] = v; s += v; sq += v * v;
    }
    __shared__ float r1[256], r2[256];
    r1[tid] = s; r2[tid] = sq;
    __syncthreads();
    for (int o = 128; o > 0; o >>= 1) {
        if (tid < o) { r1[tid] += r1[tid + o]; r2[tid] += r2[tid + o]; }
        __syncthreads();
    }
    float mean = r1[0] * (1.0f / E_);
    float var  = r2[0] * (1.0f / E_) - mean * mean;
    float rstd = rsqrtf(var + 1e-5f);
#pragma unroll
    for (int i = 0; i < 4; i++) {
        int e = tid + i * 256;
        float v = (vals[i] - mean) * rstd * g[e] + b[e];
        bf16 h, l; split2(v, h, l);
        oh[(size_t)row * E_ + e] = h;
        ol[(size_t)row * E_ + e] = l;
    }
}

// ---------------------------------------------------------------------------
// Split-precision bf16 tensor-core GEMM (ldmatrix + cp.async 3-stage) — R7 base
//   OUTMODE: 0 = fp32 out (tw.out[z], opt bias/Cin/RELU)
//            1 = split-bf16 out (Ch/Cl args)
//            2 = QKV: z=0,1 -> split out tw.oh/ol[z] [row][N]; z=2 -> transposed
// ---------------------------------------------------------------------------
struct TriW {
    const bf16* bh[3];
    const bf16* bl[3];
    float*      out[3];
    bf16*       oh[3];
    bf16*       ol[3];
};

#define SMEM_STAGE_ELEMS 20480      // 4 * 128 * 40
#define SMEM_ARR_ELEMS   5120       // 128 * 40

template <int NGUARD>
__device__ __forceinline__ void issue_stage(
    uint32_t smem_u32, int stage, int kt,
    const bf16* __restrict__ gAh, const bf16* __restrict__ gAl,
    const bf16* __restrict__ gBh, const bf16* __restrict__ gBl,
    int K, int limB, int tid) {
    // R7-proven mapping: 64 rows x 4 chunks(16B) per pass, 2 passes -> 128 rows,
    // full 32-bf16 (64B) K-width per row.
    int row = tid >> 2;          // 0..63
    int c   = tid & 3;           // 16B chunk within 64B row
    int koff = kt * 32 + c * 8;
    uint32_t base = smem_u32 + (uint32_t)stage * (SMEM_STAGE_ELEMS * 2);
#pragma unroll
    for (int hfl = 0; hfl < 2; hfl++) {
        int r = row + hfl * 64;
        uint32_t doff = (uint32_t)(r * 40 + c * 8) * 2;
        cp16(base + 0 * (SMEM_ARR_ELEMS * 2) + doff, gAh + (size_t)r * K + koff);
        cp16(base + 1 * (SMEM_ARR_ELEMS * 2) + doff, gAl + (size_t)r * K + koff);
        int rb = NGUARD ? ((r < limB) ? r : 0) : r;
        cp16(base + 2 * (SMEM_ARR_ELEMS * 2) + doff, gBh + (size_t)rb * K + koff);
        cp16(base + 3 * (SMEM_ARR_ELEMS * 2) + doff, gBl + (size_t)rb * K + koff);
    }
}

template <int RELU, int OUTMODE, int NGUARD>
__global__ void __launch_bounds__(256) mma_gemm(
    const bf16* __restrict__ Ah, const bf16* __restrict__ Al,
    TriW tw,
    const float* __restrict__ bias, const float* __restrict__ Cin,
    bf16* __restrict__ Ch, bf16* __restrict__ Cl,
    int M, int N, int K) {
    __shared__ bf16 sm[3][4][128][40];
    const uint32_t smem_u32 = smem_addr_u32(&sm[0][0][0][0]);

    const int z = blockIdx.z;
    const bf16* __restrict__ Bh = tw.bh[z];
    const bf16* __restrict__ Bl = tw.bl[z];

    const int tid  = threadIdx.x;
    const int lane = tid & 31;
    const int warp = tid >> 5;
    const int wm = warp >> 2;            // 0..1
    const int wn = warp & 3;             // 0..3
    const int l15 = lane & 15;
    const int lhi = lane >> 4;           // 0/1
    const int gid = lane >> 2, t4 = lane & 3;
    const int m0 = blockIdx.y * 128, n0 = blockIdx.x * 128;

    const bf16* gAh = Ah + (size_t)m0 * K;
    const bf16* gAl = Al + (size_t)m0 * K;
    const bf16* gBh = Bh + (size_t)n0 * K;
    const bf16* gBl = Bl + (size_t)n0 * K;
    const int limB = N - n0;

    float acc[4][4][4];
#pragma unroll
    for (int i = 0; i < 4; i++)
#pragma unroll
        for (int j = 0; j < 4; j++)
#pragma unroll
            for (int e = 0; e < 4; e++) acc[i][j][e] = 0.f;

    const int nk = K >> 5;   // K / 32

    issue_stage<NGUARD>(smem_u32, 0, 0, gAh, gAl, gBh, gBl, K, limB, tid);
    cp_commit();
    issue_stage<NGUARD>(smem_u32, 1, 1, gAh, gAl, gBh, gBl, K, limB, tid);
    cp_commit();

    for (int kt = 0; kt < nk; kt++) {
        if (kt + 2 < nk)
            issue_stage<NGUARD>(smem_u32, (kt + 2) % 3, kt + 2,
                                gAh, gAl, gBh, gBl, K, limB, tid);
        cp_commit();
        cp_wait2();
        __syncthreads();

        const uint32_t stageB = smem_u32 + (uint32_t)(kt % 3) * (SMEM_STAGE_ELEMS * 2);
#pragma unroll
        for (int ks = 0; ks < 2; ks++) {
            uint32_t afh[4][4], afl[4][4], bfh[2][4], bfl[2][4];
#pragma unroll
            for (int i = 0; i < 4; i++) {
                uint32_t ra = stageB +
                    (uint32_t)((wm * 64 + i * 16 + l15) * 40 + ks * 16 + lhi * 8) * 2;
                LDSM4(afh[i][0], afh[i][1], afh[i][2], afh[i][3], ra);
                LDSM4(afl[i][0], afl[i][1], afl[i][2], afl[i][3],
                      ra + (SMEM_ARR_ELEMS * 2));
            }
#pragma unroll
            for (int jj = 0; jj < 2; jj++) {
                uint32_t rb = stageB + 2 * (SMEM_ARR_ELEMS * 2) +
                    (uint32_t)((wn * 32 + jj * 16 + l15) * 40 + ks * 16 + lhi * 8) * 2;
                LDSM4(bfh[jj][0], bfh[jj][1], bfh[jj][2], bfh[jj][3], rb);
                LDSM4(bfl[jj][0], bfl[jj][1], bfl[jj][2], bfl[jj][3],
                      rb + (SMEM_ARR_ELEMS * 2));
            }
#pragma unroll
            for (int j = 0; j < 4; j++) {
                const int jj = j >> 1, sel = j & 1;
                const uint32_t b0h = bfh[jj][sel], b1h = bfh[jj][sel + 2];
                const uint32_t b0l = bfl[jj][sel], b1l = bfl[jj][sel + 2];
#pragma unroll
                for (int i = 0; i < 4; i++) MMA_BF16(acc[i][j], afh[i], b0h, b1h);
#pragma unroll
                for (int i = 0; i < 4; i++) MMA_BF16(acc[i][j], afh[i], b0l, b1l);
#pragma unroll
                for (int i = 0; i < 4; i++) MMA_BF16(acc[i][j], afl[i], b0h, b1h);
            }
        }
        __syncthreads();
    }

    // epilogue
    float* __restrict__ Cf = tw.out[z];
    bf16* __restrict__ Qoh = tw.oh[z];
    bf16* __restrict__ Qol = tw.ol[z];
#pragma unroll
    for (int i = 0; i < 4; i++) {
#pragma unroll
        for (int j = 0; j < 4; j++) {
            const int colb = n0 + wn * 32 + j * 8 + 2 * t4;
            if (NGUARD && colb >= N) continue;
#pragma unroll
            for (int half = 0; half < 2; half++) {
                const int row = m0 + wm * 64 + i * 16 + gid + half * 8;
                float v0 = acc[i][j][half * 2 + 0];
                float v1 = acc[i][j][half * 2 + 1];
                if (bias) { v0 += bias[colb]; v1 += bias[colb + 1]; }
                if (Cin) {
                    float2 ci = *(const float2*)&Cin[(size_t)row * N + colb];
                    v0 += ci.x; v1 += ci.y;
                }
                if (RELU) { v0 = fmaxf(v0, 0.f); v1 = fmaxf(v1, 0.f); }
                if (OUTMODE == 1) {
                    bf16 h0, l0, h1, l1;
                    split2(v0, h0, l0); split2(v1, h1, l1);
                    __nv_bfloat162 ph; ph.x = h0; ph.y = h1;
                    __nv_bfloat162 pl; pl.x = l0; pl.y = l1;
                    *(__nv_bfloat162*)&Ch[(size_t)row * N + colb] = ph;
                    *(__nv_bfloat162*)&Cl[(size_t)row * N + colb] = pl;
                } else if (OUTMODE == 2) {
                    bf16 h0, l0, h1, l1;
                    split2(v0, h0, l0); split2(v1, h1, l1);
                    if (z < 2) {
                        __nv_bfloat162 ph; ph.x = h0; ph.y = h1;
                        __nv_bfloat162 pl; pl.x = l0; pl.y = l1;
                        *(__nv_bfloat162*)&Qoh[(size_t)row * N + colb] = ph;
                        *(__nv_bfloat162*)&Qol[(size_t)row * N + colb] = pl;
                    } else {   // transposed V: [col][row], leading dim M
                        Qoh[(size_t)colb * M + row] = h0;
                        Qoh[(size_t)(colb + 1) * M + row] = h1;
                        Qol[(size_t)colb * M + row] = l0;
                        Qol[(size_t)(colb + 1) * M + row] = l1;
                    }
                } else {
                    float2 o; o.x = v0; o.y = v1;
                    *(float2*)&Cf[(size_t)row * N + colb] = o;
                }
            }
        }
    }
}

// ---------------------------------------------------------------------------
// Fused causal flash attention (split-bf16 mma, online base-2 softmax)
// CTA: 64 q-rows of one (b,h); 128 threads (4 warps x 16 rows).
// K tiles of 64 keys, double-buffered cp.async.
// ---------------------------------------------------------------------------
#define FA_PITCHB 144                 // 72 bf16 per row
#define FA_ARR    (64 * FA_PITCHB)    // 9216 B per 64x64 tile
#define FA_KV_OFF (2 * FA_ARR)        // after Qh, Ql
#define FA_STAGE  (4 * FA_ARR)        // Kh, Kl, Vh, Vl
#define FA_SMEM   (FA_KV_OFF + 2 * FA_STAGE)   // 92160 B

__device__ __forceinline__ void fa_issue_kv(
    uint32_t sb, int stage, int kt, int b, int h, int tid,
    const bf16* __restrict__ kh, const bf16* __restrict__ kl,
    const bf16* __restrict__ vth, const bf16* __restrict__ vtl) {
    uint32_t base = sb + FA_KV_OFF + (uint32_t)stage * FA_STAGE;
    int rowp = tid >> 3;        // 0..15
    int c16  = tid & 7;
#pragma unroll
    for (int rep = 0; rep < 4; rep++) {
        int r = rep * 16 + rowp;
        uint32_t doff = (uint32_t)(r * FA_PITCHB + c16 * 16);
        size_t kidx = ((size_t)b * T_ + kt * 64 + r) * E_ + h * 64 + c16 * 8;
        cp16(base + 0 * FA_ARR + doff, kh + kidx);
        cp16(base + 1 * FA_ARR + doff, kl + kidx);
        size_t vidx = (size_t)(h * 64 + r) * MTOK + (size_t)b * T_ + kt * 64 + c16 * 8;
        cp16(base + 2 * FA_ARR + doff, vth + vidx);
        cp16(base + 3 * FA_ARR + doff, vtl + vidx);
    }
}

__global__ void __launch_bounds__(128) flash_kernel(
    const bf16* __restrict__ qh, const bf16* __restrict__ ql,
    const bf16* __restrict__ kh, const bf16* __restrict__ kl,
    const bf16* __restrict__ vth, const bf16* __restrict__ vtl,
    bf16* __restrict__ ath, bf16* __restrict__ atl) {
    extern __shared__ char fsm[];
    const uint32_t sb = smem_addr_u32(fsm);
    const int bh = blockIdx.y;
    const int b = bh >> 4, h = bh & 15;
    const int r0 = blockIdx.x * 64;
    const int tid = threadIdx.x;
    const int w = tid >> 5, lane = tid & 31;
    const int l15 = lane & 15, lhi = lane >> 4;
    const int g = lane >> 2, t4 = lane & 3;
    const size_t qrow0 = (size_t)b * T_ + r0;

    // Q tile load (h/l)
    {
        int rowp = tid >> 3;
        int c16 = tid & 7;
#pragma unroll
        for (int rep = 0; rep < 4; rep++) {
            int r = rep * 16 + rowp;
            uint32_t doff = (uint32_t)(r * FA_PITCHB + c16 * 16);
            size_t qidx = (qrow0 + r) * E_ + h * 64 + c16 * 8;
            cp16(sb + doff, qh + qidx);
            cp16(sb + FA_ARR + doff, ql + qidx);
        }
    }
    fa_issue_kv(sb, 0, 0, b, h, tid, kh, kl, vth, vtl);
    cp_commit();                       // group 0: Q + stage0

    const int nt = r0 / 64 + 1;
    const float CC = 0.18033688011112042f;   // 0.125 * log2(e)

    float m2g = -1e30f, m2g8 = -1e30f;
    float lg = 0.f, lg8 = 0.f;
    float oacc[8][4];
#pragma unroll
    for (int jd = 0; jd < 8; jd++)
#pragma unroll
        for (int e = 0; e < 4; e++) oacc[jd][e] = 0.f;
    uint32_t qfh[4][4], qfl[4][4];

    for (int kt = 0; kt < nt; kt++) {
        if (kt + 1 < nt)
            fa_issue_kv(sb, (kt + 1) & 1, kt + 1, b, h, tid, kh, kl, vth, vtl);
        cp_commit();
        cp_wait1();
        __syncthreads();

        if (kt == 0) {
#pragma unroll
            for (int kk = 0; kk < 4; kk++) {
                uint32_t ra = sb + (uint32_t)((16 * w + l15) * FA_PITCHB + kk * 32 + lhi * 16);
                LDSM4(qfh[kk][0], qfh[kk][1], qfh[kk][2], qfh[kk][3], ra);
                LDSM4(qfl[kk][0], qfl[kk][1], qfl[kk][2], qfl[kk][3], ra + FA_ARR);
            }
        }

        const uint32_t kbreg = sb + FA_KV_OFF + (uint32_t)(kt & 1) * FA_STAGE;

        // S = Q K^T  (split: QhKh + QhKl + QlKh)
        float sc[8][4];
#pragma unroll
        for (int j = 0; j < 8; j++)
#pragma unroll
            for (int e = 0; e < 4; e++) sc[j][e] = 0.f;
#pragma unroll
        for (int ks = 0; ks < 4; ks++) {
            uint32_t kfh[4][4], kfl[4][4];
#pragma unroll
            for (int jj = 0; jj < 4; jj++) {
                uint32_t rb = kbreg + (uint32_t)((jj * 16 + l15) * FA_PITCHB + ks * 32 + lhi * 16);
                LDSM4(kfh[jj][0], kfh[jj][1], kfh[jj][2], kfh[jj][3], rb);
                LDSM4(kfl[jj][0], kfl[jj][1], kfl[jj][2], kfl[jj][3], rb + FA_ARR);
            }
#pragma unroll
            for (int j = 0; j < 8; j++) {
                const int jj = j >> 1, sel = j & 1;
                MMA_BF16(sc[j], qfh[ks], kfh[jj][sel], kfh[jj][sel + 2]);
                MMA_BF16(sc[j], qfh[ks], kfl[jj][sel], kfl[jj][sel + 2]);
                MMA_BF16(sc[j], qfl[ks], kfh[jj][sel], kfh[jj][sel + 2]);
            }
        }

        // scale + causal mask (diagonal tile only)
#pragma unroll
        for (int j = 0; j < 8; j++)
#pragma unroll
            for (int e = 0; e < 4; e++) sc[j][e] *= CC;
        if (kt == nt - 1) {
            const int kbase = kt * 64;
#pragma unroll
            for (int j = 0; j < 8; j++) {
#pragma unroll
                for (int e = 0; e < 4; e++) {
                    int col = kbase + 8 * j + 2 * t4 + (e & 1);
                    int row = r0 + 16 * w + g + ((e >> 1) ? 8 : 0);
                    if (col > row) sc[j][e] = -1e30f;
                }
            }
        }

        // online softmax (base 2)
        float rg = -1e30f, rg8 = -1e30f;
#pragma unroll
        for (int j = 0; j < 8; j++) {
            rg  = fmaxf(rg,  fmaxf(sc[j][0], sc[j][1]));
            rg8 = fmaxf(rg8, fmaxf(sc[j][2], sc[j][3]));
        }
        rg  = fmaxf(rg,  __shfl_xor_sync(0xffffffffu, rg, 1));
        rg  = fmaxf(rg,  __shfl_xor_sync(0xffffffffu, rg, 2));
        rg8 = fmaxf(rg8, __shfl_xor_sync(0xffffffffu, rg8, 1));
        rg8 = fmaxf(rg8, __shfl_xor_sync(0xffffffffu, rg8, 2));
        float m2gn = fmaxf(m2g, rg), m2g8n = fmaxf(m2g8, rg8);
        float ag  = fexp2(m2g - m2gn);
        float ag8 = fexp2(m2g8 - m2g8n);
        m2g = m2gn; m2g8 = m2g8n;

        float sumg = 0.f, sumg8 = 0.f;
        uint32_t aph[4][4], apl[4][4];
#pragma unroll
        for (int j = 0; j < 8; j++) {
            float p0 = fexp2(sc[j][0] - m2g);
            float p1 = fexp2(sc[j][1] - m2g);
            float p2 = fexp2(sc[j][2] - m2g8);
            float p3 = fexp2(sc[j][3] - m2g8);
            sumg += p0 + p1; sumg8 += p2 + p3;
            bf16 h0 = __float2bfloat16_rn(p0), h1 = __float2bfloat16_rn(p1);
            bf16 h2 = __float2bfloat16_rn(p2), h3 = __float2bfloat16_rn(p3);
            float e0 = p0 - __bfloat162float(h0), e1 = p1 - __bfloat162float(h1);
            float e2 = p2 - __bfloat162float(h2), e3 = p3 - __bfloat162float(h3);
            const int kk = j >> 1;
            const int base = (j & 1) ? 2 : 0;
            aph[kk][base + 0] = pk2(h0, h1);
            aph[kk][base + 1] = pk2(h2, h3);
            apl[kk][base + 0] = pk2(__float2bfloat16_rn(e0), __float2bfloat16_rn(e1));
            apl[kk][base + 1] = pk2(__float2bfloat16_rn(e2), __float2bfloat16_rn(e3));
        }
        lg = lg * ag + sumg; lg8 = lg8 * ag8 + sumg8;
#pragma unroll
        for (int jd = 0; jd < 8; jd++) {
            oacc[jd][0] *= ag;  oacc[jd][1] *= ag;
            oacc[jd][2] *= ag8; oacc[jd][3] *= ag8;
        }

        // O += P V   (split: PhVh + PhVl + PlVh), V tile is [d][token]
        const uint32_t vbreg = kbreg + 2 * FA_ARR;
#pragma unroll
        for (int ks = 0; ks < 4; ks++) {
            uint32_t vfh[4][4], vfl[4][4];
#pragma unroll
            for (int jj = 0; jj < 4; jj++) {
                uint32_t rb = vbreg + (uint32_t)((jj * 16 + l15) * FA_PITCHB + ks * 32 + lhi * 16);
                LDSM4(vfh[jj][0], vfh[jj][1], vfh[jj][2], vfh[jj][3], rb);
                LDSM4(vfl[jj][0], vfl[jj][1], vfl[jj][2], vfl[jj][3], rb + FA_ARR);
            }
#pragma unroll
            for (int jd = 0; jd < 8; jd++) {
                const int jj = jd >> 1, sel = jd & 1;
                MMA_BF16(oacc[jd], aph[ks], vfh[jj][sel], vfh[jj][sel + 2]);
                MMA_BF16(oacc[jd], aph[ks], vfl[jj][sel], vfl[jj][sel + 2]);
                MMA_BF16(oacc[jd], apl[ks], vfh[jj][sel], vfh[jj][sel + 2]);
            }
        }
        __syncthreads();
    }

    // finalize: full row sums + normalize + split-bf16 store
    lg  += __shfl_xor_sync(0xffffffffu, lg, 1);
    lg  += __shfl_xor_sync(0xffffffffu, lg, 2);
    lg8 += __shfl_xor_sync(0xffffffffu, lg8, 1);
    lg8 += __shfl_xor_sync(0xffffffffu, lg8, 2);
    float ig = 1.0f / lg, ig8 = 1.0f / lg8;

    const size_t rowg  = qrow0 + 16 * w + g;
    const size_t rowg8 = rowg + 8;
#pragma unroll
    for (int jd = 0; jd < 8; jd++) {
        int col = h * 64 + 8 * jd + 2 * t4;
        float o0 = oacc[jd][0] * ig,  o1 = oacc[jd][1] * ig;
        float o2 = oacc[jd][2] * ig8, o3 = oacc[jd][3] * ig8;
        bf16 h0, l0, h1, l1, h2, l2, h3, l3;
        split2(o0, h0, l0); split2(o1, h1, l1);
        split2(o2, h2, l2); split2(o3, h3, l3);
        __nv_bfloat162 ph0; ph0.x = h0; ph0.y = h1;
        __nv_bfloat162 pl0; pl0.x = l0; pl0.y = l1;
        __nv_bfloat162 ph1; ph1.x = h2; ph1.y = h3;
        __nv_bfloat162 pl1; pl1.x = l2; pl1.y = l3;
        *(__nv_bfloat162*)&ath[rowg * E_ + col]  = ph0;
        *(__nv_bfloat162*)&atl[rowg * E_ + col]  = pl0;
        *(__nv_bfloat162*)&ath[rowg8 * E_ + col] = ph1;
        *(__nv_bfloat162*)&atl[rowg8 * E_ + col] = pl1;
    }
}

// ---------------------------------------------------------------------------
// Launch
// ---------------------------------------------------------------------------
extern "C" void kernel_launch(void* const* d_in, const int* in_sizes, int n_in,
                              void* d_out, int out_size) {
    const float* idx  = (const float*)d_in[0];
    const float* tok  = (const float*)d_in[1];
    const float* posW = (const float*)d_in[2];
    const float* posb = (const float*)d_in[3];
    const float* Wq   = (const float*)d_in[4];
    const float* Wk   = (const float*)d_in[5];
    const float* Wv   = (const float*)d_in[6];
    const float* Wo   = (const float*)d_in[7];
    const float* bo   = (const float*)d_in[8];
    const float* W1   = (const float*)d_in[9];
    const float* b1   = (const float*)d_in[10];
    const float* W2   = (const float*)d_in[11];
    const float* b2   = (const float*)d_in[12];
    const float* ln1g = (const float*)d_in[13];
    const float* ln1b = (const float*)d_in[14];
    const float* ln2g = (const float*)d_in[15];
    const float* ln2b = (const float*)d_in[16];
    const float* lnfg = (const float*)d_in[17];
    const float* lnfb = (const float*)d_in[18];
    const float* lmW  = (const float*)d_in[19];
    const float* lmb  = (const float*)d_in[20];
    float* out = (float*)d_out;

    float *x;
    bf16 *hh, *hl, *qhp, *qlp, *khp, *klp, *vth, *vtl, *ath, *atl, *mh, *ml;
    bf16 *wqh, *wql, *wkh, *wkl, *wvh, *wvl, *woh, *wol, *w1h, *w1l, *w2h, *w2l, *lmh, *lml;
    cudaGetSymbolAddress((void**)&x,   g_x);
    cudaGetSymbolAddress((void**)&hh,  g_h_h);
    cudaGetSymbolAddress((void**)&hl,  g_h_l);
    cudaGetSymbolAddress((void**)&qhp, g_q_h);  cudaGetSymbolAddress((void**)&qlp, g_q_l);
    cudaGetSymbolAddress((void**)&khp, g_k_h);  cudaGetSymbolAddress((void**)&klp, g_k_l);
    cudaGetSymbolAddress((void**)&vth, g_vT_h); cudaGetSymbolAddress((void**)&vtl, g_vT_l);
    cudaGetSymbolAddress((void**)&ath, g_attn_h);
    cudaGetSymbolAddress((void**)&atl, g_attn_l);
    cudaGetSymbolAddress((void**)&mh,  g_mlp_h);
    cudaGetSymbolAddress((void**)&ml,  g_mlp_l);
    cudaGetSymbolAddress((void**)&wqh, g_wq_h); cudaGetSymbolAddress((void**)&wql, g_wq_l);
    cudaGetSymbolAddress((void**)&wkh, g_wk_h); cudaGetSymbolAddress((void**)&wkl, g_wk_l);
    cudaGetSymbolAddress((void**)&wvh, g_wv_h); cudaGetSymbolAddress((void**)&wvl, g_wv_l);
    cudaGetSymbolAddress((void**)&woh, g_wo_h); cudaGetSymbolAddress((void**)&wol, g_wo_l);
    cudaGetSymbolAddress((void**)&w1h, g_w1_h); cudaGetSymbolAddress((void**)&w1l, g_w1_l);
    cudaGetSymbolAddress((void**)&w2h, g_w2_h); cudaGetSymbolAddress((void**)&w2l, g_w2_l);
    cudaGetSymbolAddress((void**)&lmh, g_lm_h); cudaGetSymbolAddress((void**)&lml, g_lm_l);

    cudaFuncSetAttribute(flash_kernel,
                         cudaFuncAttributeMaxDynamicSharedMemorySize, FA_SMEM);

    // weight transpose+split, batched over layers
    dim3 tb(32, 8);
    tsplit_kernel<<<dim3(E_ / 32, E_ / 32, L_), tb>>>(Wq, wqh, wql, E_, E_, (size_t)E_ * E_);
    tsplit_kernel<<<dim3(E_ / 32, E_ / 32, L_), tb>>>(Wk, wkh, wkl, E_, E_, (size_t)E_ * E_);
    tsplit_kernel<<<dim3(E_ / 32, E_ / 32, L_), tb>>>(Wv, wvh, wvl, E_, E_, (size_t)E_ * E_);
    tsplit_kernel<<<dim3(E_ / 32, E_ / 32, L_), tb>>>(Wo, woh, wol, E_, E_, (size_t)E_ * E_);
    tsplit_kernel<<<dim3(FF / 32, E_ / 32, L_), tb>>>(W1, w1h, w1l, E_, FF, (size_t)E_ * FF);
    tsplit_kernel<<<dim3(E_ / 32, FF / 32, L_), tb>>>(W2, w2h, w2l, FF, E_, (size_t)E_ * FF);
    tsplit_kernel<<<dim3(V_ / 32, E_ / 32, 1), tb>>>(lmW, lmh, lml, E_, V_, 0);

    embed_kernel<<<MTOK, 256>>>(idx, tok, posW, posb, x);

    dim3 gQKV(E_ / 128, MTOK / 128, 3);       // (8,16,3)
    dim3 gEE(E_ / 128, MTOK / 128, 1);        // (8,16)
    dim3 gEF(FF / 128, MTOK / 128, 1);        // (32,16)
    dim3 gVg((V_ + 127) / 128, MTOK / 128, 1);// (7,16)
    dim3 gFA(T_ / 64, B_ * H_);               // (16,32)

    for (int l = 0; l < L_; l++) {
        size_t oEE = (size_t)l * E_ * E_;
        size_t oEF = (size_t)l * E_ * FF;

        ln_split_kernel<<<MTOK, 256>>>(x, ln1g + l * E_, ln1b + l * E_, hh, hl);

        TriW qkv = {};
        qkv.bh[0] = wqh + oEE; qkv.bl[0] = wql + oEE; qkv.oh[0] = qhp; qkv.ol[0] = qlp;
        qkv.bh[1] = wkh + oEE; qkv.bl[1] = wkl + oEE; qkv.oh[1] = khp; qkv.ol[1] = klp;
        qkv.bh[2] = wvh + oEE; qkv.bl[2] = wvl + oEE; qkv.oh[2] = vth; qkv.ol[2] = vtl;
        mma_gemm<0, 2, 0><<<gQKV, 256>>>(
            hh, hl, qkv, nullptr, nullptr, nullptr, nullptr, MTOK, E_, E_);

        flash_kernel<<<gFA, 128, FA_SMEM>>>(qhp, qlp, khp, klp, vth, vtl, ath, atl);

        TriW wo = {};
        wo.bh[0] = woh + oEE; wo.bl[0] = wol + oEE; wo.out[0] = x;
        wo.bh[1] = wo.bh[0]; wo.bl[1] = wo.bl[0]; wo.out[1] = x;
        wo.bh[2] = wo.bh[0]; wo.bl[2] = wo.bl[0]; wo.out[2] = x;
        mma_gemm<0, 0, 0><<<gEE, 256>>>(
            ath, atl, wo, bo + l * E_, x, nullptr, nullptr, MTOK, E_, E_);

        ln_split_kernel<<<MTOK, 256>>>(x, ln2g + l * E_, ln2b + l * E_, hh, hl);

        TriW w1 = {};
        w1.bh[0] = w1h + oEF; w1.bl[0] = w1l + oEF;
        w1.bh[1] = w1.bh[0]; w1.bl[1] = w1.bl[0];
        w1.bh[2] = w1.bh[0]; w1.bl[2] = w1.bl[0];
        mma_gemm<1, 1, 0><<<gEF, 256>>>(
            hh, hl, w1, b1 + l * FF, nullptr, mh, ml, MTOK, FF, E_);

        TriW w2 = {};
        w2.bh[0] = w2h + oEF; w2.bl[0] = w2l + oEF; w2.out[0] = x;
        w2.bh[1] = w2.bh[0]; w2.bl[1] = w2.bl[0]; w2.out[1] = x;
        w2.bh[2] = w2.bh[0]; w2.bl[2] = w2.bl[0]; w2.out[2] = x;
        mma_gemm<0, 0, 0><<<gEE, 256>>>(
            mh, ml, w2, b2 + l * E_, x, nullptr, nullptr, MTOK, E_, FF);
    }
    ln_split_kernel<<<MTOK, 256>>>(x, lnfg, lnfb, hh, hl);

    TriW lm = {};
    lm.bh[0] = lmh; lm.bl[0] = lml; lm.out[0] = out;
    lm.bh[1] = lm.bh[0]; lm.bl[1] = lm.bl[0]; lm.out[1] = out;
    lm.bh[2] = lm.bh[0]; lm.bl[2] = lm.bl[0]; lm.out[2] = out;
    mma_gemm<0, 0, 1><<<gVg, 256>>>(
        hh, hl, lm, lmb, nullptr, nullptr, nullptr, MTOK, V_, E_);
}

// round 14
// speedup vs baseline: 2.3010x; 1.0011x over previous
#include <cuda_runtime.h>
#include <cuda_bf16.h>
#include <math.h>
#include <stdint.h>
#include <string.h>

// Problem constants
#define L_    8
#define H_    16
#define E_    1024
#define T_    1024
#define B_    2
#define V_    800
#define D_    64
#define MTOK  2048      // B*T
#define FF    4096      // 4*E

typedef __nv_bfloat16 bf16;

// ---------------------------------------------------------------------------
// Scratch (device globals: allocation-free per harness rules)
// ---------------------------------------------------------------------------
__device__ float g_x[MTOK * E_];                   // residual stream (fp32)

// split-bf16 activations
__device__ bf16 g_h_h[MTOK * E_];
__device__ bf16 g_h_l[MTOK * E_];
__device__ bf16 g_q_h[MTOK * E_];
__device__ bf16 g_q_l[MTOK * E_];
__device__ bf16 g_k_h[MTOK * E_];
__device__ bf16 g_k_l[MTOK * E_];
__device__ bf16 g_vT_h[(size_t)E_ * MTOK];         // transposed V: [E][MTOK]
__device__ bf16 g_vT_l[(size_t)E_ * MTOK];
__device__ bf16 g_attn_h[MTOK * E_];
__device__ bf16 g_attn_l[MTOK * E_];
__device__ bf16 g_mlp_h[(size_t)MTOK * FF];
__device__ bf16 g_mlp_l[(size_t)MTOK * FF];

// split + transposed weights  ([N][K] row-major)
__device__ bf16 g_wq_h[(size_t)L_ * E_ * E_];
__device__ bf16 g_wq_l[(size_t)L_ * E_ * E_];
__device__ bf16 g_wk_h[(size_t)L_ * E_ * E_];
__device__ bf16 g_wk_l[(size_t)L_ * E_ * E_];
__device__ bf16 g_wv_h[(size_t)L_ * E_ * E_];
__device__ bf16 g_wv_l[(size_t)L_ * E_ * E_];
__device__ bf16 g_wo_h[(size_t)L_ * E_ * E_];
__device__ bf16 g_wo_l[(size_t)L_ * E_ * E_];
__device__ bf16 g_w1_h[(size_t)L_ * E_ * FF];
__device__ bf16 g_w1_l[(size_t)L_ * E_ * FF];
__device__ bf16 g_w2_h[(size_t)L_ * E_ * FF];
__device__ bf16 g_w2_l[(size_t)L_ * E_ * FF];
__device__ bf16 g_lm_h[(size_t)E_ * V_];
__device__ bf16 g_lm_l[(size_t)E_ * V_];

__device__ __forceinline__ void split2(float v, bf16& h, bf16& l) {
    h = __float2bfloat16_rn(v);
    l = __float2bfloat16_rn(v - __bfloat162float(h));
}

__device__ __forceinline__ uint32_t pk2(bf16 a, bf16 b) {
    __nv_bfloat162 t; t.x = a; t.y = b;
    uint32_t r; memcpy(&r, &t, 4); return r;
}

// fast 2^y for y <= 0 (clamped at -120): magic-number round + deg-5 poly
__device__ __forceinline__ float fexp2(float y) {
    y = fmaxf(y, -120.f);
    float t = y + 12582912.f;                    // round-to-nearest int
    int n = __float_as_int(t) - 0x4B400000;
    float f = y - (t - 12582912.f);              // f in [-0.5, 0.5]
    float p = 1.33335814645e-3f;
    p = fmaf(p, f, 9.61812910763e-3f);
    p = fmaf(p, f, 5.55041086648e-2f);
    p = fmaf(p, f, 2.40226506959e-1f);
    p = fmaf(p, f, 6.93147180560e-1f);
    p = fmaf(p, f, 1.0f);
    return __int_as_float(__float_as_int(p) + (n << 23));
}

// ---------------------------------------------------------------------------
// mma / ldmatrix / cp.async primitives (legacy path — proven on this target)
// ---------------------------------------------------------------------------
#define MMA_BF16(c, a, b0v, b1v)                                              \
    asm volatile(                                                             \
        "mma.sync.aligned.m16n8k16.row.col.f32.bf16.bf16.f32 "                \
        "{%0,%1,%2,%3}, {%4,%5,%6,%7}, {%8,%9}, {%0,%1,%2,%3};\n"             \
        : "+f"((c)[0]), "+f"((c)[1]), "+f"((c)[2]), "+f"((c)[3])              \
        : "r"((a)[0]), "r"((a)[1]), "r"((a)[2]), "r"((a)[3]),                 \
          "r"(b0v), "r"(b1v))

#define LDSM4(r0, r1, r2, r3, addr)                                           \
    asm volatile("ldmatrix.sync.aligned.m8n8.x4.shared.b16 {%0,%1,%2,%3}, [%4];" \
        : "=r"(r0), "=r"(r1), "=r"(r2), "=r"(r3) : "r"(addr))

__device__ __forceinline__ uint32_t smem_addr_u32(const void* p) {
    uint32_t a;
    asm("{ .reg .u64 t; cvta.to.shared.u64 t, %1; cvt.u32.u64 %0, t; }"
        : "=r"(a) : "l"(p));
    return a;
}
__device__ __forceinline__ void cp16(uint32_t dst, const void* src) {
    asm volatile("cp.async.cg.shared.global [%0], [%1], 16;\n" :: "r"(dst), "l"(src));
}
__device__ __forceinline__ void cp_commit() {
    asm volatile("cp.async.commit_group;\n");
}
__device__ __forceinline__ void cp_wait1() {
    asm volatile("cp.async.wait_group 1;\n");
}
__device__ __forceinline__ void cp_wait2() {
    asm volatile("cp.async.wait_group 2;\n");
}

// ---------------------------------------------------------------------------
// Transpose + split: W[K][N] fp32 -> Th/Tl [N][K] bf16, batched over layers (z)
// ---------------------------------------------------------------------------
__global__ void tsplit_kernel(const float* __restrict__ W,
                              bf16* __restrict__ Th, bf16* __restrict__ Tl,
                              int K, int N, size_t zstride) {
    const float* Wz = W + (size_t)blockIdx.z * zstride;
    bf16* Thz = Th + (size_t)blockIdx.z * zstride;
    bf16* Tlz = Tl + (size_t)blockIdx.z * zstride;
    __shared__ float t[32][33];
    int n0 = blockIdx.x * 32, k0 = blockIdx.y * 32;
    int tx = threadIdx.x, ty = threadIdx.y;   // 32 x 8
#pragma unroll
    for (int r = 0; r < 4; r++)
        t[ty + r * 8][tx] = Wz[(size_t)(k0 + ty + r * 8) * N + n0 + tx];
    __syncthreads();
#pragma unroll
    for (int r = 0; r < 4; r++) {
        int n = n0 + ty + r * 8;
        int k = k0 + tx;
        float v = t[tx][ty + r * 8];
        bf16 h, l; split2(v, h, l);
        Thz[(size_t)n * K + k] = h;
        Tlz[(size_t)n * K + k] = l;
    }
}

// ---------------------------------------------------------------------------
// Embedding (fp32 residual)
// ---------------------------------------------------------------------------
__global__ void embed_kernel(const float* __restrict__ idx,
                             const float* __restrict__ tok_table,
                             const float* __restrict__ posW,
                             const float* __restrict__ posb,
                             float* __restrict__ x) {
    int row = blockIdx.x;
    float lat = idx[row * 3 + 0];
    float lon = idx[row * 3 + 1];
    float wl  = idx[row * 3 + 2];
    float f = rintf(wl * 100.0f - 300.0f);
    f = fminf(fmaxf(f, 0.0f), (float)(V_ - 1));
    int tok = (int)f;
    const float* te = tok_table + (size_t)tok * E_;
    for (int e = threadIdx.x; e < E_; e += blockDim.x)
        x[(size_t)row * E_ + e] = te[e] + lat * posW[e] + lon * posW[E_ + e] + posb[e];
}

// ---------------------------------------------------------------------------
// LayerNorm -> split-bf16 output
// ---------------------------------------------------------------------------
__global__ void ln_split_kernel(const float* __restrict__ in,
                                const float* __restrict__ g,
                                const float* __restrict__ b,
                                bf16* __restrict__ oh, bf16* __restrict__ ol) {
    int row = blockIdx.x;
    int tid = threadIdx.x;
    const float* px = in + (size_t)row * E_;
    float vals[4];
    float s = 0.f, sq = 0.f;
#pragma unroll
    for (int i = 0; i < 4; i++) {
        float v = px[tid + i * 256];
        vals[i] = v; s += v; sq += v * v;
    }
    __shared__ float r1[256], r2[256];
    r1[tid] = s; r2[tid] = sq;
    __syncthreads();
    for (int o = 128; o > 0; o >>= 1) {
        if (tid < o) { r1[tid] += r1[tid + o]; r2[tid] += r2[tid + o]; }
        __syncthreads();
    }
    float mean = r1[0] * (1.0f / E_);
    float var  = r2[0] * (1.0f / E_) - mean * mean;
    float rstd = rsqrtf(var + 1e-5f);
#pragma unroll
    for (int i = 0; i < 4; i++) {
        int e = tid + i * 256;
        float v = (vals[i] - mean) * rstd * g[e] + b[e];
        bf16 h, l; split2(v, h, l);
        oh[(size_t)row * E_ + e] = h;
        ol[(size_t)row * E_ + e] = l;
    }
}

// ---------------------------------------------------------------------------
// Split-precision bf16 tensor-core GEMM (ldmatrix + cp.async 3-stage) — R7 base
//   OUTMODE: 0 = fp32 out (tw.out[z], opt bias/Cin/RELU)
//            1 = split-bf16 out (Ch/Cl args)
//            2 = QKV: z=0,1 -> split out tw.oh/ol[z] [row][N]; z=2 -> transposed
// ---------------------------------------------------------------------------
struct TriW {
    const bf16* bh[3];
    const bf16* bl[3];
    float*      out[3];
    bf16*       oh[3];
    bf16*       ol[3];
};

#define SMEM_STAGE_ELEMS 20480      // 4 * 128 * 40
#define SMEM_ARR_ELEMS   5120       // 128 * 40

template <int NGUARD>
__device__ __forceinline__ void issue_stage(
    uint32_t smem_u32, int stage, int kt,
    const bf16* __restrict__ gAh, const bf16* __restrict__ gAl,
    const bf16* __restrict__ gBh, const bf16* __restrict__ gBl,
    int K, int limB, int tid) {
    // R7-proven mapping: 64 rows x 4 chunks(16B) per pass, 2 passes -> 128 rows,
    // full 32-bf16 (64B) K-width per row.
    int row = tid >> 2;          // 0..63
    int c   = tid & 3;           // 16B chunk within 64B row
    int koff = kt * 32 + c * 8;
    uint32_t base = smem_u32 + (uint32_t)stage * (SMEM_STAGE_ELEMS * 2);
#pragma unroll
    for (int hfl = 0; hfl < 2; hfl++) {
        int r = row + hfl * 64;
        uint32_t doff = (uint32_t)(r * 40 + c * 8) * 2;
        cp16(base + 0 * (SMEM_ARR_ELEMS * 2) + doff, gAh + (size_t)r * K + koff);
        cp16(base + 1 * (SMEM_ARR_ELEMS * 2) + doff, gAl + (size_t)r * K + koff);
        int rb = NGUARD ? ((r < limB) ? r : 0) : r;
        cp16(base + 2 * (SMEM_ARR_ELEMS * 2) + doff, gBh + (size_t)rb * K + koff);
        cp16(base + 3 * (SMEM_ARR_ELEMS * 2) + doff, gBl + (size_t)rb * K + koff);
    }
}

template <int RELU, int OUTMODE, int NGUARD>
__global__ void __launch_bounds__(256) mma_gemm(
    const bf16* __restrict__ Ah, const bf16* __restrict__ Al,
    TriW tw,
    const float* __restrict__ bias, const float* __restrict__ Cin,
    bf16* __restrict__ Ch, bf16* __restrict__ Cl,
    int M, int N, int K) {
    __shared__ bf16 sm[3][4][128][40];
    const uint32_t smem_u32 = smem_addr_u32(&sm[0][0][0][0]);

    const int z = blockIdx.z;
    const bf16* __restrict__ Bh = tw.bh[z];
    const bf16* __restrict__ Bl = tw.bl[z];

    const int tid  = threadIdx.x;
    const int lane = tid & 31;
    const int warp = tid >> 5;
    const int wm = warp >> 2;            // 0..1
    const int wn = warp & 3;             // 0..3
    const int l15 = lane & 15;
    const int lhi = lane >> 4;           // 0/1
    const int gid = lane >> 2, t4 = lane & 3;
    const int m0 = blockIdx.y * 128, n0 = blockIdx.x * 128;

    const bf16* gAh = Ah + (size_t)m0 * K;
    const bf16* gAl = Al + (size_t)m0 * K;
    const bf16* gBh = Bh + (size_t)n0 * K;
    const bf16* gBl = Bl + (size_t)n0 * K;
    const int limB = N - n0;

    float acc[4][4][4];
#pragma unroll
    for (int i = 0; i < 4; i++)
#pragma unroll
        for (int j = 0; j < 4; j++)
#pragma unroll
            for (int e = 0; e < 4; e++) acc[i][j][e] = 0.f;

    const int nk = K >> 5;   // K / 32

    issue_stage<NGUARD>(smem_u32, 0, 0, gAh, gAl, gBh, gBl, K, limB, tid);
    cp_commit();
    issue_stage<NGUARD>(smem_u32, 1, 1, gAh, gAl, gBh, gBl, K, limB, tid);
    cp_commit();

    for (int kt = 0; kt < nk; kt++) {
        if (kt + 2 < nk)
            issue_stage<NGUARD>(smem_u32, (kt + 2) % 3, kt + 2,
                                gAh, gAl, gBh, gBl, K, limB, tid);
        cp_commit();
        cp_wait2();
        __syncthreads();

        const uint32_t stageB = smem_u32 + (uint32_t)(kt % 3) * (SMEM_STAGE_ELEMS * 2);
#pragma unroll
        for (int ks = 0; ks < 2; ks++) {
            uint32_t afh[4][4], afl[4][4], bfh[2][4], bfl[2][4];
#pragma unroll
            for (int i = 0; i < 4; i++) {
                uint32_t ra = stageB +
                    (uint32_t)((wm * 64 + i * 16 + l15) * 40 + ks * 16 + lhi * 8) * 2;
                LDSM4(afh[i][0], afh[i][1], afh[i][2], afh[i][3], ra);
                LDSM4(afl[i][0], afl[i][1], afl[i][2], afl[i][3],
                      ra + (SMEM_ARR_ELEMS * 2));
            }
#pragma unroll
            for (int jj = 0; jj < 2; jj++) {
                uint32_t rb = stageB + 2 * (SMEM_ARR_ELEMS * 2) +
                    (uint32_t)((wn * 32 + jj * 16 + l15) * 40 + ks * 16 + lhi * 8) * 2;
                LDSM4(bfh[jj][0], bfh[jj][1], bfh[jj][2], bfh[jj][3], rb);
                LDSM4(bfl[jj][0], bfl[jj][1], bfl[jj][2], bfl[jj][3],
                      rb + (SMEM_ARR_ELEMS * 2));
            }
#pragma unroll
            for (int j = 0; j < 4; j++) {
                const int jj = j >> 1, sel = j & 1;
                const uint32_t b0h = bfh[jj][sel], b1h = bfh[jj][sel + 2];
                const uint32_t b0l = bfl[jj][sel], b1l = bfl[jj][sel + 2];
#pragma unroll
                for (int i = 0; i < 4; i++) MMA_BF16(acc[i][j], afh[i], b0h, b1h);
#pragma unroll
                for (int i = 0; i < 4; i++) MMA_BF16(acc[i][j], afh[i], b0l, b1l);
#pragma unroll
                for (int i = 0; i < 4; i++) MMA_BF16(acc[i][j], afl[i], b0h, b1h);
            }
        }
        __syncthreads();
    }

    // epilogue
    float* __restrict__ Cf = tw.out[z];
    bf16* __restrict__ Qoh = tw.oh[z];
    bf16* __restrict__ Qol = tw.ol[z];
#pragma unroll
    for (int i = 0; i < 4; i++) {
#pragma unroll
        for (int j = 0; j < 4; j++) {
            const int colb = n0 + wn * 32 + j * 8 + 2 * t4;
            if (NGUARD && colb >= N) continue;
#pragma unroll
            for (int half = 0; half < 2; half++) {
                const int row = m0 + wm * 64 + i * 16 + gid + half * 8;
                float v0 = acc[i][j][half * 2 + 0];
                float v1 = acc[i][j][half * 2 + 1];
                if (bias) { v0 += bias[colb]; v1 += bias[colb + 1]; }
                if (Cin) {
                    float2 ci = *(const float2*)&Cin[(size_t)row * N + colb];
                    v0 += ci.x; v1 += ci.y;
                }
                if (RELU) { v0 = fmaxf(v0, 0.f); v1 = fmaxf(v1, 0.f); }
                if (OUTMODE == 1) {
                    bf16 h0, l0, h1, l1;
                    split2(v0, h0, l0); split2(v1, h1, l1);
                    __nv_bfloat162 ph; ph.x = h0; ph.y = h1;
                    __nv_bfloat162 pl; pl.x = l0; pl.y = l1;
                    *(__nv_bfloat162*)&Ch[(size_t)row * N + colb] = ph;
                    *(__nv_bfloat162*)&Cl[(size_t)row * N + colb] = pl;
                } else if (OUTMODE == 2) {
                    bf16 h0, l0, h1, l1;
                    split2(v0, h0, l0); split2(v1, h1, l1);
                    if (z < 2) {
                        __nv_bfloat162 ph; ph.x = h0; ph.y = h1;
                        __nv_bfloat162 pl; pl.x = l0; pl.y = l1;
                        *(__nv_bfloat162*)&Qoh[(size_t)row * N + colb] = ph;
                        *(__nv_bfloat162*)&Qol[(size_t)row * N + colb] = pl;
                    } else {   // transposed V: [col][row], leading dim M
                        Qoh[(size_t)colb * M + row] = h0;
                        Qoh[(size_t)(colb + 1) * M + row] = h1;
                        Qol[(size_t)colb * M + row] = l0;
                        Qol[(size_t)(colb + 1) * M + row] = l1;
                    }
                } else {
                    float2 o; o.x = v0; o.y = v1;
                    *(float2*)&Cf[(size_t)row * N + colb] = o;
                }
            }
        }
    }
}

// ---------------------------------------------------------------------------
// Fused causal flash attention (split-bf16 mma, online base-2 softmax)
// CTA: 64 q-rows of one (b,h); 128 threads (4 warps x 16 rows).
// K tiles of 64 keys, double-buffered cp.async.
// ---------------------------------------------------------------------------
#define FA_PITCHB 144                 // 72 bf16 per row
#define FA_ARR    (64 * FA_PITCHB)    // 9216 B per 64x64 tile
#define FA_KV_OFF (2 * FA_ARR)        // after Qh, Ql
#define FA_STAGE  (4 * FA_ARR)        // Kh, Kl, Vh, Vl
#define FA_SMEM   (FA_KV_OFF + 2 * FA_STAGE)   // 92160 B

__device__ __forceinline__ void fa_issue_kv(
    uint32_t sb, int stage, int kt, int b, int h, int tid,
    const bf16* __restrict__ kh, const bf16* __restrict__ kl,
    const bf16* __restrict__ vth, const bf16* __restrict__ vtl) {
    uint32_t base = sb + FA_KV_OFF + (uint32_t)stage * FA_STAGE;
    int rowp = tid >> 3;        // 0..15
    int c16  = tid & 7;
#pragma unroll
    for (int rep = 0; rep < 4; rep++) {
        int r = rep * 16 + rowp;
        uint32_t doff = (uint32_t)(r * FA_PITCHB + c16 * 16);
        size_t kidx = ((size_t)b * T_ + kt * 64 + r) * E_ + h * 64 + c16 * 8;
        cp16(base + 0 * FA_ARR + doff, kh + kidx);
        cp16(base + 1 * FA_ARR + doff, kl + kidx);
        size_t vidx = (size_t)(h * 64 + r) * MTOK + (size_t)b * T_ + kt * 64 + c16 * 8;
        cp16(base + 2 * FA_ARR + doff, vth + vidx);
        cp16(base + 3 * FA_ARR + doff, vtl + vidx);
    }
}

__global__ void __launch_bounds__(128) flash_kernel(
    const bf16* __restrict__ qh, const bf16* __restrict__ ql,
    const bf16* __restrict__ kh, const bf16* __restrict__ kl,
    const bf16* __restrict__ vth, const bf16* __restrict__ vtl,
    bf16* __restrict__ ath, bf16* __restrict__ atl) {
    extern __shared__ char fsm[];
    const uint32_t sb = smem_addr_u32(fsm);
    const int bh = blockIdx.y;
    const int b = bh >> 4, h = bh & 15;
    const int r0 = blockIdx.x * 64;
    const int tid = threadIdx.x;
    const int w = tid >> 5, lane = tid & 31;
    const int l15 = lane & 15, lhi = lane >> 4;
    const int g = lane >> 2, t4 = lane & 3;
    const size_t qrow0 = (size_t)b * T_ + r0;

    // Q tile load (h/l)
    {
        int rowp = tid >> 3;
        int c16 = tid & 7;
#pragma unroll
        for (int rep = 0; rep < 4; rep++) {
            int r = rep * 16 + rowp;
            uint32_t doff = (uint32_t)(r * FA_PITCHB + c16 * 16);
            size_t qidx = (qrow0 + r) * E_ + h * 64 + c16 * 8;
            cp16(sb + doff, qh + qidx);
            cp16(sb + FA_ARR + doff, ql + qidx);
        }
    }
    fa_issue_kv(sb, 0, 0, b, h, tid, kh, kl, vth, vtl);
    cp_commit();                       // group 0: Q + stage0

    const int nt = r0 / 64 + 1;
    const float CC = 0.18033688011112042f;   // 0.125 * log2(e)

    float m2g = -1e30f, m2g8 = -1e30f;
    float lg = 0.f, lg8 = 0.f;
    float oacc[8][4];
#pragma unroll
    for (int jd = 0; jd < 8; jd++)
#pragma unroll
        for (int e = 0; e < 4; e++) oacc[jd][e] = 0.f;
    uint32_t qfh[4][4], qfl[4][4];

    for (int kt = 0; kt < nt; kt++) {
        if (kt + 1 < nt)
            fa_issue_kv(sb, (kt + 1) & 1, kt + 1, b, h, tid, kh, kl, vth, vtl);
        cp_commit();
        cp_wait1();
        __syncthreads();

        if (kt == 0) {
#pragma unroll
            for (int kk = 0; kk < 4; kk++) {
                uint32_t ra = sb + (uint32_t)((16 * w + l15) * FA_PITCHB + kk * 32 + lhi * 16);
                LDSM4(qfh[kk][0], qfh[kk][1], qfh[kk][2], qfh[kk][3], ra);
                LDSM4(qfl[kk][0], qfl[kk][1], qfl[kk][2], qfl[kk][3], ra + FA_ARR);
            }
        }

        const uint32_t kbreg = sb + FA_KV_OFF + (uint32_t)(kt & 1) * FA_STAGE;

        // S = Q K^T  (split: QhKh + QhKl + QlKh)
        float sc[8][4];
#pragma unroll
        for (int j = 0; j < 8; j++)
#pragma unroll
            for (int e = 0; e < 4; e++) sc[j][e] = 0.f;
#pragma unroll
        for (int ks = 0; ks < 4; ks++) {
            uint32_t kfh[4][4], kfl[4][4];
#pragma unroll
            for (int jj = 0; jj < 4; jj++) {
                uint32_t rb = kbreg + (uint32_t)((jj * 16 + l15) * FA_PITCHB + ks * 32 + lhi * 16);
                LDSM4(kfh[jj][0], kfh[jj][1], kfh[jj][2], kfh[jj][3], rb);
                LDSM4(kfl[jj][0], kfl[jj][1], kfl[jj][2], kfl[jj][3], rb + FA_ARR);
            }
#pragma unroll
            for (int j = 0; j < 8; j++) {
                const int jj = j >> 1, sel = j & 1;
                MMA_BF16(sc[j], qfh[ks], kfh[jj][sel], kfh[jj][sel + 2]);
                MMA_BF16(sc[j], qfh[ks], kfl[jj][sel], kfl[jj][sel + 2]);
                MMA_BF16(sc[j], qfl[ks], kfh[jj][sel], kfh[jj][sel + 2]);
            }
        }

        // scale + causal mask (diagonal tile only)
#pragma unroll
        for (int j = 0; j < 8; j++)
#pragma unroll
            for (int e = 0; e < 4; e++) sc[j][e] *= CC;
        if (kt == nt - 1) {
            const int kbase = kt * 64;
#pragma unroll
            for (int j = 0; j < 8; j++) {
#pragma unroll
                for (int e = 0; e < 4; e++) {
                    int col = kbase + 8 * j + 2 * t4 + (e & 1);
                    int row = r0 + 16 * w + g + ((e >> 1) ? 8 : 0);
                    if (col > row) sc[j][e] = -1e30f;
                }
            }
        }

        // online softmax (base 2)
        float rg = -1e30f, rg8 = -1e30f;
#pragma unroll
        for (int j = 0; j < 8; j++) {
            rg  = fmaxf(rg,  fmaxf(sc[j][0], sc[j][1]));
            rg8 = fmaxf(rg8, fmaxf(sc[j][2], sc[j][3]));
        }
        rg  = fmaxf(rg,  __shfl_xor_sync(0xffffffffu, rg, 1));
        rg  = fmaxf(rg,  __shfl_xor_sync(0xffffffffu, rg, 2));
        rg8 = fmaxf(rg8, __shfl_xor_sync(0xffffffffu, rg8, 1));
        rg8 = fmaxf(rg8, __shfl_xor_sync(0xffffffffu, rg8, 2));
        float m2gn = fmaxf(m2g, rg), m2g8n = fmaxf(m2g8, rg8);
        float ag  = fexp2(m2g - m2gn);
        float ag8 = fexp2(m2g8 - m2g8n);
        m2g = m2gn; m2g8 = m2g8n;

        float sumg = 0.f, sumg8 = 0.f;
        uint32_t aph[4][4], apl[4][4];
#pragma unroll
        for (int j = 0; j < 8; j++) {
            float p0 = fexp2(sc[j][0] - m2g);
            float p1 = fexp2(sc[j][1] - m2g);
            float p2 = fexp2(sc[j][2] - m2g8);
            float p3 = fexp2(sc[j][3] - m2g8);
            sumg += p0 + p1; sumg8 += p2 + p3;
            bf16 h0 = __float2bfloat16_rn(p0), h1 = __float2bfloat16_rn(p1);
            bf16 h2 = __float2bfloat16_rn(p2), h3 = __float2bfloat16_rn(p3);
            float e0 = p0 - __bfloat162float(h0), e1 = p1 - __bfloat162float(h1);
            float e2 = p2 - __bfloat162float(h2), e3 = p3 - __bfloat162float(h3);
            const int kk = j >> 1;
            const int base = (j & 1) ? 2 : 0;
            aph[kk][base + 0] = pk2(h0, h1);
            aph[kk][base + 1] = pk2(h2, h3);
            apl[kk][base + 0] = pk2(__float2bfloat16_rn(e0), __float2bfloat16_rn(e1));
            apl[kk][base + 1] = pk2(__float2bfloat16_rn(e2), __float2bfloat16_rn(e3));
        }
        lg = lg * ag + sumg; lg8 = lg8 * ag8 + sumg8;
#pragma unroll
        for (int jd = 0; jd < 8; jd++) {
            oacc[jd][0] *= ag;  oacc[jd][1] *= ag;
            oacc[jd][2] *= ag8; oacc[jd][3] *= ag8;
        }

        // O += P V   (split: PhVh + PhVl + PlVh), V tile is [d][token]
        const uint32_t vbreg = kbreg + 2 * FA_ARR;
#pragma unroll
        for (int ks = 0; ks < 4; ks++) {
            uint32_t vfh[4][4], vfl[4][4];
#pragma unroll
            for (int jj = 0; jj < 4; jj++) {
                uint32_t rb = vbreg + (uint32_t)((jj * 16 + l15) * FA_PITCHB + ks * 32 + lhi * 16);
                LDSM4(vfh[jj][0], vfh[jj][1], vfh[jj][2], vfh[jj][3], rb);
                LDSM4(vfl[jj][0], vfl[jj][1], vfl[jj][2], vfl[jj][3], rb + FA_ARR);
            }
#pragma unroll
            for (int jd = 0; jd < 8; jd++) {
                const int jj = jd >> 1, sel = jd & 1;
                MMA_BF16(oacc[jd], aph[ks], vfh[jj][sel], vfh[jj][sel + 2]);
                MMA_BF16(oacc[jd], aph[ks], vfl[jj][sel], vfl[jj][sel + 2]);
                MMA_BF16(oacc[jd], apl[ks], vfh[jj][sel], vfh[jj][sel + 2]);
            }
        }
        __syncthreads();
    }

    // finalize: full row sums + normalize + split-bf16 store
    lg  += __shfl_xor_sync(0xffffffffu, lg, 1);
    lg  += __shfl_xor_sync(0xffffffffu, lg, 2);
    lg8 += __shfl_xor_sync(0xffffffffu, lg8, 1);
    lg8 += __shfl_xor_sync(0xffffffffu, lg8, 2);
    float ig = 1.0f / lg, ig8 = 1.0f / lg8;

    const size_t rowg  = qrow0 + 16 * w + g;
    const size_t rowg8 = rowg + 8;
#pragma unroll
    for (int jd = 0; jd < 8; jd++) {
        int col = h * 64 + 8 * jd + 2 * t4;
        float o0 = oacc[jd][0] * ig,  o1 = oacc[jd][1] * ig;
        float o2 = oacc[jd][2] * ig8, o3 = oacc[jd][3] * ig8;
        bf16 h0, l0, h1, l1, h2, l2, h3, l3;
        split2(o0, h0, l0); split2(o1, h1, l1);
        split2(o2, h2, l2); split2(o3, h3, l3);
        __nv_bfloat162 ph0; ph0.x = h0; ph0.y = h1;
        __nv_bfloat162 pl0; pl0.x = l0; pl0.y = l1;
        __nv_bfloat162 ph1; ph1.x = h2; ph1.y = h3;
        __nv_bfloat162 pl1; pl1.x = l2; pl1.y = l3;
        *(__nv_bfloat162*)&ath[rowg * E_ + col]  = ph0;
        *(__nv_bfloat162*)&atl[rowg * E_ + col]  = pl0;
        *(__nv_bfloat162*)&ath[rowg8 * E_ + col] = ph1;
        *(__nv_bfloat162*)&atl[rowg8 * E_ + col] = pl1;
    }
}

// ---------------------------------------------------------------------------
// Launch
// ---------------------------------------------------------------------------
extern "C" void kernel_launch(void* const* d_in, const int* in_sizes, int n_in,
                              void* d_out, int out_size) {
    const float* idx  = (const float*)d_in[0];
    const float* tok  = (const float*)d_in[1];
    const float* posW = (const float*)d_in[2];
    const float* posb = (const float*)d_in[3];
    const float* Wq   = (const float*)d_in[4];
    const float* Wk   = (const float*)d_in[5];
    const float* Wv   = (const float*)d_in[6];
    const float* Wo   = (const float*)d_in[7];
    const float* bo   = (const float*)d_in[8];
    const float* W1   = (const float*)d_in[9];
    const float* b1   = (const float*)d_in[10];
    const float* W2   = (const float*)d_in[11];
    const float* b2   = (const float*)d_in[12];
    const float* ln1g = (const float*)d_in[13];
    const float* ln1b = (const float*)d_in[14];
    const float* ln2g = (const float*)d_in[15];
    const float* ln2b = (const float*)d_in[16];
    const float* lnfg = (const float*)d_in[17];
    const float* lnfb = (const float*)d_in[18];
    const float* lmW  = (const float*)d_in[19];
    const float* lmb  = (const float*)d_in[20];
    float* out = (float*)d_out;

    float *x;
    bf16 *hh, *hl, *qhp, *qlp, *khp, *klp, *vth, *vtl, *ath, *atl, *mh, *ml;
    bf16 *wqh, *wql, *wkh, *wkl, *wvh, *wvl, *woh, *wol, *w1h, *w1l, *w2h, *w2l, *lmh, *lml;
    cudaGetSymbolAddress((void**)&x,   g_x);
    cudaGetSymbolAddress((void**)&hh,  g_h_h);
    cudaGetSymbolAddress((void**)&hl,  g_h_l);
    cudaGetSymbolAddress((void**)&qhp, g_q_h);  cudaGetSymbolAddress((void**)&qlp, g_q_l);
    cudaGetSymbolAddress((void**)&khp, g_k_h);  cudaGetSymbolAddress((void**)&klp, g_k_l);
    cudaGetSymbolAddress((void**)&vth, g_vT_h); cudaGetSymbolAddress((void**)&vtl, g_vT_l);
    cudaGetSymbolAddress((void**)&ath, g_attn_h);
    cudaGetSymbolAddress((void**)&atl, g_attn_l);
    cudaGetSymbolAddress((void**)&mh,  g_mlp_h);
    cudaGetSymbolAddress((void**)&ml,  g_mlp_l);
    cudaGetSymbolAddress((void**)&wqh, g_wq_h); cudaGetSymbolAddress((void**)&wql, g_wq_l);
    cudaGetSymbolAddress((void**)&wkh, g_wk_h); cudaGetSymbolAddress((void**)&wkl, g_wk_l);
    cudaGetSymbolAddress((void**)&wvh, g_wv_h); cudaGetSymbolAddress((void**)&wvl, g_wv_l);
    cudaGetSymbolAddress((void**)&woh, g_wo_h); cudaGetSymbolAddress((void**)&wol, g_wo_l);
    cudaGetSymbolAddress((void**)&w1h, g_w1_h); cudaGetSymbolAddress((void**)&w1l, g_w1_l);
    cudaGetSymbolAddress((void**)&w2h, g_w2_h); cudaGetSymbolAddress((void**)&w2l, g_w2_l);
    cudaGetSymbolAddress((void**)&lmh, g_lm_h); cudaGetSymbolAddress((void**)&lml, g_lm_l);

    cudaFuncSetAttribute(flash_kernel,
                         cudaFuncAttributeMaxDynamicSharedMemorySize, FA_SMEM);

    // weight transpose+split, batched over layers
    dim3 tb(32, 8);
    tsplit_kernel<<<dim3(E_ / 32, E_ / 32, L_), tb>>>(Wq, wqh, wql, E_, E_, (size_t)E_ * E_);
    tsplit_kernel<<<dim3(E_ / 32, E_ / 32, L_), tb>>>(Wk, wkh, wkl, E_, E_, (size_t)E_ * E_);
    tsplit_kernel<<<dim3(E_ / 32, E_ / 32, L_), tb>>>(Wv, wvh, wvl, E_, E_, (size_t)E_ * E_);
    tsplit_kernel<<<dim3(E_ / 32, E_ / 32, L_), tb>>>(Wo, woh, wol, E_, E_, (size_t)E_ * E_);
    tsplit_kernel<<<dim3(FF / 32, E_ / 32, L_), tb>>>(W1, w1h, w1l, E_, FF, (size_t)E_ * FF);
    tsplit_kernel<<<dim3(E_ / 32, FF / 32, L_), tb>>>(W2, w2h, w2l, FF, E_, (size_t)E_ * FF);
    tsplit_kernel<<<dim3(V_ / 32, E_ / 32, 1), tb>>>(lmW, lmh, lml, E_, V_, 0);

    embed_kernel<<<MTOK, 256>>>(idx, tok, posW, posb, x);

    dim3 gQKV(E_ / 128, MTOK / 128, 3);       // (8,16,3)
    dim3 gEE(E_ / 128, MTOK / 128, 1);        // (8,16)
    dim3 gEF(FF / 128, MTOK / 128, 1);        // (32,16)
    dim3 gVg((V_ + 127) / 128, MTOK / 128, 1);// (7,16)
    dim3 gFA(T_ / 64, B_ * H_);               // (16,32)

    for (int l = 0; l < L_; l++) {
        size_t oEE = (size_t)l * E_ * E_;
        size_t oEF = (size_t)l * E_ * FF;

        ln_split_kernel<<<MTOK, 256>>>(x, ln1g + l * E_, ln1b + l * E_, hh, hl);

        TriW qkv = {};
        qkv.bh[0] = wqh + oEE; qkv.bl[0] = wql + oEE; qkv.oh[0] = qhp; qkv.ol[0] = qlp;
        qkv.bh[1] = wkh + oEE; qkv.bl[1] = wkl + oEE; qkv.oh[1] = khp; qkv.ol[1] = klp;
        qkv.bh[2] = wvh + oEE; qkv.bl[2] = wvl + oEE; qkv.oh[2] = vth; qkv.ol[2] = vtl;
        mma_gemm<0, 2, 0><<<gQKV, 256>>>(
            hh, hl, qkv, nullptr, nullptr, nullptr, nullptr, MTOK, E_, E_);

        flash_kernel<<<gFA, 128, FA_SMEM>>>(qhp, qlp, khp, klp, vth, vtl, ath, atl);

        TriW wo = {};
        wo.bh[0] = woh + oEE; wo.bl[0] = wol + oEE; wo.out[0] = x;
        wo.bh[1] = wo.bh[0]; wo.bl[1] = wo.bl[0]; wo.out[1] = x;
        wo.bh[2] = wo.bh[0]; wo.bl[2] = wo.bl[0]; wo.out[2] = x;
        mma_gemm<0, 0, 0><<<gEE, 256>>>(
            ath, atl, wo, bo + l * E_, x, nullptr, nullptr, MTOK, E_, E_);

        ln_split_kernel<<<MTOK, 256>>>(x, ln2g + l * E_, ln2b + l * E_, hh, hl);

        TriW w1 = {};
        w1.bh[0] = w1h + oEF; w1.bl[0] = w1l + oEF;
        w1.bh[1] = w1.bh[0]; w1.bl[1] = w1.bl[0];
        w1.bh[2] = w1.bh[0]; w1.bl[2] = w1.bl[0];
        mma_gemm<1, 1, 0><<<gEF, 256>>>(
            hh, hl, w1, b1 + l * FF, nullptr, mh, ml, MTOK, FF, E_);

        TriW w2 = {};
        w2.bh[0] = w2h + oEF; w2.bl[0] = w2l + oEF; w2.out[0] = x;
        w2.bh[1] = w2.bh[0]; w2.bl[1] = w2.bl[0]; w2.out[1] = x;
        w2.bh[2] = w2.bh[0]; w2.bl[2] = w2.bl[0]; w2.out[2] = x;
        mma_gemm<0, 0, 0><<<gEE, 256>>>(
            mh, ml, w2, b2 + l * E_, x, nullptr, nullptr, MTOK, E_, FF);
    }
    ln_split_kernel<<<MTOK, 256>>>(x, lnfg, lnfb, hh, hl);

    TriW lm = {};
    lm.bh[0] = lmh; lm.bl[0] = lml; lm.out[0] = out;
    lm.bh[1] = lm.bh[0]; lm.bl[1] = lm.bl[0]; lm.out[1] = out;
    lm.bh[2] = lm.bh[0]; lm.bl[2] = lm.bl[0]; lm.out[2] = out;
    mma_gemm<0, 0, 1><<<gVg, 256>>>(
        hh, hl, lm, lmb, nullptr, nullptr, nullptr, MTOK, V_, E_);
}